// round 5
// baseline (speedup 1.0000x reference)
#include <cuda_runtime.h>
#include <math.h>
#include <stdint.h>

#define NB 16
#define NS 1024
#define ND 128
#define NH 4
#define LNEPS 1e-5f

// Scratch (device globals: allocation-free per harness rules)
__device__ float g_q[NB*NH*NS*ND];            // [bh][s][d]          (logical)
__device__ float g_k[NB*NH*NS*ND];            // [bh][s][d_perm]     (pair-permuted d)
__device__ float g_v[NB*NH*NS*ND];            // [bh][d][s_perm]     (d-major, pair-permuted s)
__device__ float g_ctx[NB*NH*NS*ND];
__device__ float g_win_perm[NH*3*ND*ND];      // W_in rows, pair-permuted k
__device__ float g_wout_perm[NH*ND*ND];       // W_out rows, pair-permuted k
__device__ float g_mean[NB];
__device__ float g_rstd[NB];
__device__ float g_wsum[NH*3*ND];
__device__ unsigned long long g_mbits[NH*NS*16];
__device__ int   g_edge64;

// pair-permutation within 8-groups: logical r -> slot (r<4 ? 2r : 2r-7)
__device__ __forceinline__ int slot8(int r) { return (r < 4) ? (r << 1) : ((r << 1) - 7); }
__device__ __forceinline__ int perm8(int idx) { return (idx & ~7) | slot8(idx & 7); }

__device__ __forceinline__ uint32_t f2tf(float f) {
    uint32_t r;
    asm("cvt.rna.tf32.f32 %0, %1;" : "=r"(r) : "f"(f));
    return r;
}

__device__ __forceinline__ void mma8(float& d0, float& d1, float& d2, float& d3,
                                     uint32_t a0, uint32_t a1, uint32_t a2, uint32_t a3,
                                     uint32_t b0, uint32_t b1) {
    asm volatile("mma.sync.aligned.m16n8k8.row.col.f32.tf32.tf32.f32 "
                 "{%0,%1,%2,%3}, {%4,%5,%6,%7}, {%8,%9}, {%0,%1,%2,%3};"
                 : "+f"(d0), "+f"(d1), "+f"(d2), "+f"(d3)
                 : "r"(a0), "r"(a1), "r"(a2), "r"(a3), "r"(b0), "r"(b1));
}

__device__ __forceinline__ void cp16(float* dst_smem, const float* src_gmem) {
    uint32_t d = (uint32_t)__cvta_generic_to_shared(dst_smem);
    asm volatile("cp.async.cg.shared.global [%0], [%1], 16;" :: "r"(d), "l"(src_gmem));
}

// ---------------------------------------------------------------------------
// K1: LayerNorm stats + edge dtype sniff
// ---------------------------------------------------------------------------
__global__ void ln_stats_kernel(const float* __restrict__ x,
                                const int* __restrict__ edge) {
    int b = blockIdx.x;
    const float4* xb = (const float4*)(x + (size_t)b * NS * ND);
    const int n4 = NS * ND / 4;
    float s = 0.f, ss = 0.f;
    for (int i = threadIdx.x; i < n4; i += blockDim.x) {
        float4 v = xb[i];
        s  += v.x + v.y + v.z + v.w;
        ss += v.x*v.x + v.y*v.y + v.z*v.z + v.w*v.w;
    }
    __shared__ float sh[256], sh2[256];
    sh[threadIdx.x] = s; sh2[threadIdx.x] = ss;
    __syncthreads();
    for (int o = 128; o > 0; o >>= 1) {
        if (threadIdx.x < o) {
            sh[threadIdx.x]  += sh[threadIdx.x + o];
            sh2[threadIdx.x] += sh2[threadIdx.x + o];
        }
        __syncthreads();
    }
    if (threadIdx.x == 0) {
        float inv_n = 1.f / (float)(NS * ND);
        float mu  = sh[0] * inv_n;
        float var = sh2[0] * inv_n - mu * mu;
        g_mean[b] = mu;
        g_rstd[b] = rsqrtf(var + LNEPS);
        if (b == 0) {
            int any = 0;
            #pragma unroll
            for (int i = 0; i < 64; i++) any |= edge[2*i + 1];
            g_edge64 = (any == 0) ? 1 : 0;
        }
    }
}

// ---------------------------------------------------------------------------
// K1b: prep — edge bitmasks, W column sums, pair-permuted weight copies
// ---------------------------------------------------------------------------
__global__ void prep_kernel(const int* __restrict__ edge,
                            const float* __restrict__ W_in,
                            const float* __restrict__ W_out) {
    int blk = blockIdx.x;
    if (blk < 64) {
        int idx = blk * 256 + threadIdx.x;
        int s = idx >> 4, t64 = idx & 15;
        unsigned long long m0 = 0, m1 = 0, m2 = 0, m3 = 0;
        if (g_edge64) {
            const int4* p = (const int4*)(edge + 2*((size_t)s*NS + t64*64));
            #pragma unroll
            for (int i = 0; i < 32; i++) {
                int4 v = p[i];
                unsigned long long b0 = 1ull << (2*i), b1 = 1ull << (2*i+1);
                if (v.x == 1) m0 |= b0;  if (v.z == 1) m0 |= b1;
                if (v.x == 2) m1 |= b0;  if (v.z == 2) m1 |= b1;
                if (v.x == 3) m2 |= b0;  if (v.z == 3) m2 |= b1;
                if (v.x == 4) m3 |= b0;  if (v.z == 4) m3 |= b1;
            }
        } else {
            const int4* p = (const int4*)(edge + ((size_t)s*NS + t64*64));
            #pragma unroll
            for (int i = 0; i < 16; i++) {
                int4 v = p[i];
                int e[4] = {v.x, v.y, v.z, v.w};
                #pragma unroll
                for (int q = 0; q < 4; q++) {
                    unsigned long long b = 1ull << (4*i + q);
                    if (e[q] == 1) m0 |= b;
                    if (e[q] == 2) m1 |= b;
                    if (e[q] == 3) m2 |= b;
                    if (e[q] == 4) m3 |= b;
                }
            }
        }
        g_mbits[(0*NS + s)*16 + t64] = m0;
        g_mbits[(1*NS + s)*16 + t64] = m1;
        g_mbits[(2*NS + s)*16 + t64] = m2;
        g_mbits[(3*NS + s)*16 + t64] = m3;
    } else if (blk < 70) {
        int col = (blk - 64) * 256 + threadIdx.x;   // 0..1535
        float s = 0.f;
        const float4* p = (const float4*)(W_in + (size_t)col * ND);
        #pragma unroll
        for (int i = 0; i < 32; i++) {
            float4 v = p[i];
            s += v.x + v.y + v.z + v.w;
        }
        g_wsum[col] = s;
    } else {
        // pair-permute weight rows: dst[2r] = src[r], dst[2r+1] = src[r+4] per 8-group
        int row = (blk - 70) * 256 + threadIdx.x;   // 0..2047
        const float* src;
        float* dst;
        if (row < 1536) { src = W_in  + (size_t)row * ND;          dst = g_win_perm  + (size_t)row * ND; }
        else            { src = W_out + (size_t)(row - 1536) * ND; dst = g_wout_perm + (size_t)(row - 1536) * ND; }
        #pragma unroll
        for (int g = 0; g < 16; g++) {
            float4 lo = *(const float4*)&src[8*g];
            float4 hi = *(const float4*)&src[8*g + 4];
            *(float2*)&dst[8*g + 0] = make_float2(lo.x, hi.x);
            *(float2*)&dst[8*g + 2] = make_float2(lo.y, hi.y);
            *(float2*)&dst[8*g + 4] = make_float2(lo.z, hi.z);
            *(float2*)&dst[8*g + 6] = make_float2(lo.w, hi.w);
        }
    }
}

// ---------------------------------------------------------------------------
// Projection kernels (tf32 mma, permuted-B LDS.64 frags)
// ---------------------------------------------------------------------------
#define PJ 132
#define PROJ_SMEM_FLOATS (128*PJ + 2*64*PJ)

// K2: fused LN + QKV projection; scatters into permuted q/k/v layouts
__global__ __launch_bounds__(256, 1) void qkv_kernel(const float* __restrict__ x,
                                                     const float* __restrict__ b_in) {
    extern __shared__ float sg[];
    float* As = sg;
    float* Bs0 = sg + 128*PJ;
    float* Bs1 = sg + 128*PJ + 64*PJ;

    const int tid  = threadIdx.x;
    const int w    = tid >> 5;
    const int lane = tid & 31;
    const int r4   = lane >> 2;
    const int c4   = lane & 3;

    const int colbase = blockIdx.x * 768;
    const int m0 = blockIdx.y * 128;
    const int b  = blockIdx.y >> 3;
    const float mean = g_mean[b], rstd = g_rstd[b];
    const float mr = mean * rstd;

    #pragma unroll
    for (int i = 0; i < 16; i++) {
        int q = i * 256 + tid;
        int row = q >> 5, c = (q & 31) * 4;
        cp16(&As[row*PJ + c], &x[(size_t)(m0 + row) * ND + c]);
    }
    #pragma unroll
    for (int i = 0; i < 8; i++) {
        int q = i * 256 + tid;
        int row = q >> 5, c = (q & 31) * 4;
        cp16(&Bs0[row*PJ + c], &g_win_perm[(size_t)(colbase + row) * ND + c]);
    }
    asm volatile("cp.async.commit_group;");
    asm volatile("cp.async.wait_group 0;");
    __syncthreads();

    uint32_t Af[64];
    {
        const int rl = 16*w + r4;
        #pragma unroll
        for (int t = 0; t < 16; t++) {
            Af[4*t+0] = f2tf(As[(rl    )*PJ + 8*t + c4    ]);
            Af[4*t+1] = f2tf(As[(rl + 8)*PJ + 8*t + c4    ]);
            Af[4*t+2] = f2tf(As[(rl    )*PJ + 8*t + c4 + 4]);
            Af[4*t+3] = f2tf(As[(rl + 8)*PJ + 8*t + c4 + 4]);
        }
    }

    const int rlo = m0 + 16*w + r4;
    const int rhi = rlo + 8;
    const int slo = rlo & (NS - 1);
    const int shi = rhi & (NS - 1);
    const int splo = perm8(slo);
    const int sphi = perm8(shi);

    #define NTQ 12
    for (int nt = 0; nt < NTQ; nt++) {
        const int buf = nt & 1;
        float* Bcur = buf ? Bs1 : Bs0;
        float* Bnxt = buf ? Bs0 : Bs1;
        if (nt + 1 < NTQ) {
            const int nrow = colbase + (nt + 1) * 64;
            #pragma unroll
            for (int i = 0; i < 8; i++) {
                int q = i * 256 + tid;
                int row = q >> 5, c = (q & 31) * 4;
                cp16(&Bnxt[row*PJ + c], &g_win_perm[(size_t)(nrow + row) * ND + c]);
            }
            asm volatile("cp.async.commit_group;");
        }

        float acc[8][4];
        #pragma unroll
        for (int j = 0; j < 8; j++)
            #pragma unroll
            for (int k = 0; k < 4; k++) acc[j][k] = 0.f;

        #pragma unroll
        for (int t = 0; t < 16; t++) {
            uint32_t a0 = Af[4*t], a1 = Af[4*t+1], a2 = Af[4*t+2], a3 = Af[4*t+3];
            #pragma unroll
            for (int j = 0; j < 8; j++) {
                float2 bb = *(const float2*)&Bcur[(8*j + r4)*PJ + 8*t + 2*c4];
                mma8(acc[j][0], acc[j][1], acc[j][2], acc[j][3], a0, a1, a2, a3,
                     __float_as_uint(bb.x), __float_as_uint(bb.y));
            }
        }

        const int n0 = colbase + nt * 64;
        #pragma unroll
        for (int j = 0; j < 8; j++) {
            int colg = n0 + 8*j + 2*c4;
            float2 bias = *(const float2*)&b_in[colg];
            float2 ws   = *(const float2*)&g_wsum[colg];
            float off0 = bias.x - mr * ws.x;
            float off1 = bias.y - mr * ws.y;
            float v00 = rstd*acc[j][0] + off0, v01 = rstd*acc[j][1] + off1;
            float v10 = rstd*acc[j][2] + off0, v11 = rstd*acc[j][3] + off1;
            int hh = colg / 384;
            int r  = colg - hh * 384;
            int which = r >> 7;
            int d = r & 127;
            size_t base = ((size_t)(b*NH + hh)) * NS * ND;
            if (which == 0) {
                *(float2*)&g_q[base + (size_t)slo * ND + d] = make_float2(v00, v01);
                *(float2*)&g_q[base + (size_t)shi * ND + d] = make_float2(v10, v11);
            } else if (which == 1) {
                int dp0 = perm8(d), dp1 = perm8(d + 1);
                g_k[base + (size_t)slo * ND + dp0] = v00;
                g_k[base + (size_t)slo * ND + dp1] = v01;
                g_k[base + (size_t)shi * ND + dp0] = v10;
                g_k[base + (size_t)shi * ND + dp1] = v11;
            } else {
                // V d-major with permuted s
                g_v[base + (size_t)d       * NS + splo] = v00;
                g_v[base + (size_t)(d + 1) * NS + splo] = v01;
                g_v[base + (size_t)d       * NS + sphi] = v10;
                g_v[base + (size_t)(d + 1) * NS + sphi] = v11;
            }
        }

        if (nt + 1 < NTQ) {
            asm volatile("cp.async.wait_group 0;");
            __syncthreads();
        }
    }
}

// K4: out projection (permuted-B LDS.64 frags)
__global__ __launch_bounds__(256, 1) void outproj_kernel(const float* __restrict__ b_out,
                                                         float* __restrict__ out) {
    extern __shared__ float sg[];
    float* As = sg;
    float* Bs0 = sg + 128*PJ;
    float* Bs1 = sg + 128*PJ + 64*PJ;

    const int tid  = threadIdx.x;
    const int w    = tid >> 5;
    const int lane = tid & 31;
    const int r4   = lane >> 2;
    const int c4   = lane & 3;

    const int hh = blockIdx.x;
    const int m0 = blockIdx.y * 128;
    const int b  = blockIdx.y >> 3;
    const int s0 = m0 & (NS - 1);
    const float* Ag = g_ctx + ((size_t)(b*NH + hh) * NS + s0) * ND;
    const int colbase = hh * 128;

    #pragma unroll
    for (int i = 0; i < 16; i++) {
        int q = i * 256 + tid;
        int row = q >> 5, c = (q & 31) * 4;
        cp16(&As[row*PJ + c], &Ag[(size_t)row * ND + c]);
    }
    #pragma unroll
    for (int i = 0; i < 8; i++) {
        int q = i * 256 + tid;
        int row = q >> 5, c = (q & 31) * 4;
        cp16(&Bs0[row*PJ + c], &g_wout_perm[(size_t)(colbase + row) * ND + c]);
    }
    asm volatile("cp.async.commit_group;");
    asm volatile("cp.async.wait_group 0;");
    __syncthreads();

    uint32_t Af[64];
    {
        const int rl = 16*w + r4;
        #pragma unroll
        for (int t = 0; t < 16; t++) {
            Af[4*t+0] = f2tf(As[(rl    )*PJ + 8*t + c4    ]);
            Af[4*t+1] = f2tf(As[(rl + 8)*PJ + 8*t + c4    ]);
            Af[4*t+2] = f2tf(As[(rl    )*PJ + 8*t + c4 + 4]);
            Af[4*t+3] = f2tf(As[(rl + 8)*PJ + 8*t + c4 + 4]);
        }
    }

    const int rlo = m0 + 16*w + r4;
    const int rhi = rlo + 8;

    #pragma unroll
    for (int nt = 0; nt < 2; nt++) {
        float* Bcur = nt ? Bs1 : Bs0;
        float* Bnxt = nt ? Bs0 : Bs1;
        if (nt == 0) {
            const int nrow = colbase + 64;
            #pragma unroll
            for (int i = 0; i < 8; i++) {
                int q = i * 256 + tid;
                int row = q >> 5, c = (q & 31) * 4;
                cp16(&Bnxt[row*PJ + c], &g_wout_perm[(size_t)(nrow + row) * ND + c]);
            }
            asm volatile("cp.async.commit_group;");
        }

        float acc[8][4];
        #pragma unroll
        for (int j = 0; j < 8; j++)
            #pragma unroll
            for (int k = 0; k < 4; k++) acc[j][k] = 0.f;

        #pragma unroll
        for (int t = 0; t < 16; t++) {
            uint32_t a0 = Af[4*t], a1 = Af[4*t+1], a2 = Af[4*t+2], a3 = Af[4*t+3];
            #pragma unroll
            for (int j = 0; j < 8; j++) {
                float2 bb = *(const float2*)&Bcur[(8*j + r4)*PJ + 8*t + 2*c4];
                mma8(acc[j][0], acc[j][1], acc[j][2], acc[j][3], a0, a1, a2, a3,
                     __float_as_uint(bb.x), __float_as_uint(bb.y));
            }
        }

        const int n0 = colbase + nt * 64;
        #pragma unroll
        for (int j = 0; j < 8; j++) {
            int colg = n0 + 8*j + 2*c4;
            float2 bias = *(const float2*)&b_out[colg];
            *(float2*)&out[(size_t)rlo * (NH*ND) + colg] =
                make_float2(acc[j][0] + bias.x, acc[j][1] + bias.y);
            *(float2*)&out[(size_t)rhi * (NH*ND) + colg] =
                make_float2(acc[j][2] + bias.x, acc[j][3] + bias.y);
        }

        if (nt == 0) {
            asm volatile("cp.async.wait_group 0;");
            __syncthreads();
        }
    }
}

// ---------------------------------------------------------------------------
// K3: flash attention (tf32 mma, bitmask edges, no-max softmax,
//     pair-permuted K/V -> LDS.64 B fragments, V pre-transposed d-major)
// ---------------------------------------------------------------------------
#define KPAD 132
#define VTPAD 68
#define PPAD 68
#define OFF_K0 0
#define OFF_K1 (64*KPAD)
#define OFF_V0 (2*64*KPAD)
#define OFF_V1 (OFF_V0 + 128*VTPAD)
#define OFF_P  (OFF_V0 + 2*128*VTPAD)
#define OFF_QSTG OFF_V1
#define ATTN_SMEM_FLOATS (OFF_P + 128*PPAD)   // 43008 floats = 172032 B

__device__ __forceinline__ void load_kv_async(const float* __restrict__ Kg,
                                              const float* __restrict__ Vg,
                                              int n0, float* Ks, float* Vt, int tid) {
    #pragma unroll
    for (int i = 0; i < 8; i++) {
        int q = i * 256 + tid;
        int krow = q >> 5, kc = (q & 31) * 4;
        cp16(&Ks[krow*KPAD + kc], Kg + (size_t)(n0 + krow) * ND + kc);
        int vrow = q >> 4, vc = (q & 15) * 4;
        cp16(&Vt[vrow*VTPAD + vc], Vg + (size_t)vrow * NS + n0 + vc);
    }
}

__global__ __launch_bounds__(256, 1) void attn_kernel() {
    extern __shared__ float sm[];
    const int tid  = threadIdx.x;
    const int w    = tid >> 5;
    const int lane = tid & 31;
    const int r4   = lane >> 2;
    const int c4   = lane & 3;

    const int bh = blockIdx.x >> 3;
    const int qt = blockIdx.x & 7;
    const int h  = bh & 3;
    const int m0 = qt * 128;
    const float scale = 0.08838834764831845f;

    const float* Qg = g_q + (size_t)bh * NS * ND;
    const float* Kg = g_k + (size_t)bh * NS * ND;
    const float* Vg = g_v + (size_t)bh * NS * ND;   // d-major

    load_kv_async(Kg, Vg, 0, sm + OFF_K0, sm + OFF_V0, tid);
    asm volatile("cp.async.commit_group;");

    {
        float* Qstg = sm + OFF_QSTG;
        #pragma unroll
        for (int i = 0; i < 16; i++) {
            int q = i * 256 + tid;
            int row = q >> 5, cc = q & 31;
            *(float4*)&Qstg[row*KPAD + cc*4] =
                *(const float4*)&Qg[(size_t)(m0 + row) * ND + cc*4];
        }
    }
    __syncthreads();

    uint32_t Qf[64];
    {
        const float* Qstg = sm + OFF_QSTG;
        const int rl = 16*w + r4;
        #pragma unroll
        for (int t = 0; t < 16; t++) {
            Qf[4*t+0] = f2tf(Qstg[(rl    )*KPAD + 8*t + c4    ] * scale);
            Qf[4*t+1] = f2tf(Qstg[(rl + 8)*KPAD + 8*t + c4    ] * scale);
            Qf[4*t+2] = f2tf(Qstg[(rl    )*KPAD + 8*t + c4 + 4] * scale);
            Qf[4*t+3] = f2tf(Qstg[(rl + 8)*KPAD + 8*t + c4 + 4] * scale);
        }
    }
    __syncthreads();

    float o[16][4];
    #pragma unroll
    for (int j = 0; j < 16; j++)
        #pragma unroll
        for (int k = 0; k < 4; k++) o[j][k] = 0.f;
    float rs_lo = 0.f, rs_hi = 0.f;

    float* Psw = sm + OFF_P + w * 16 * PPAD;
    const int mlo = m0 + 16*w + r4;
    const int mhi = mlo + 8;
    const unsigned long long* mb_lo_base = &g_mbits[((size_t)h*NS + mlo)*16];
    const unsigned long long* mb_hi_base = &g_mbits[((size_t)h*NS + mhi)*16];

    for (int it = 0; it < 16; ++it) {
        const int buf = it & 1;
        if (it + 1 < 16) {
            load_kv_async(Kg, Vg, (it + 1) * 64,
                          sm + (buf ? OFF_K0 : OFF_K1),
                          sm + (buf ? OFF_V0 : OFF_V1), tid);
            asm volatile("cp.async.commit_group;");
            asm volatile("cp.async.wait_group 1;");
        } else {
            asm volatile("cp.async.wait_group 0;");
        }
        __syncthreads();

        const unsigned long long mb_lo = mb_lo_base[it];
        const unsigned long long mb_hi = mb_hi_base[it];

        const float* Ks = sm + (buf ? OFF_K1 : OFF_K0);
        const float* Vt = sm + (buf ? OFF_V1 : OFF_V0);

        // ---- QK^T (Q pre-scaled); K pair-permuted -> LDS.64 B frags ----
        float acc[8][4];
        #pragma unroll
        for (int j = 0; j < 8; j++)
            #pragma unroll
            for (int k = 0; k < 4; k++) acc[j][k] = 0.f;

        #pragma unroll
        for (int t = 0; t < 16; t++) {
            uint32_t a0 = Qf[4*t], a1 = Qf[4*t+1], a2 = Qf[4*t+2], a3 = Qf[4*t+3];
            #pragma unroll
            for (int j = 0; j < 8; j++) {
                float2 bb = *(const float2*)&Ks[(8*j + r4)*KPAD + 8*t + 2*c4];
                mma8(acc[j][0], acc[j][1], acc[j][2], acc[j][3], a0, a1, a2, a3,
                     __float_as_uint(bb.x), __float_as_uint(bb.y));
            }
        }

        // ---- exp + mask-select + P store ----
        #pragma unroll
        for (int j = 0; j < 8; j++) {
            unsigned blo = (unsigned)(mb_lo >> (8*j + 2*c4));
            unsigned bhi = (unsigned)(mb_hi >> (8*j + 2*c4));
            float p0 = (blo & 1u) ? __expf(acc[j][0]) : 0.f;
            float p1 = (blo & 2u) ? __expf(acc[j][1]) : 0.f;
            float p2 = (bhi & 1u) ? __expf(acc[j][2]) : 0.f;
            float p3 = (bhi & 2u) ? __expf(acc[j][3]) : 0.f;
            rs_lo += p0 + p1;
            rs_hi += p2 + p3;
            uint32_t u0 = f2tf(p0), u1 = f2tf(p1), u2 = f2tf(p2), u3 = f2tf(p3);
            *(uint2*)&Psw[(r4    )*PPAD + 8*j + 2*c4] = make_uint2(u0, u1);
            *(uint2*)&Psw[(r4 + 8)*PPAD + 8*j + 2*c4] = make_uint2(u2, u3);
        }
        __syncwarp();

        // ---- O += P @ V ; V d-major + key-permuted -> LDS.64 B frags ----
        #pragma unroll
        for (int t = 0; t < 8; t++) {
            uint32_t a0 = __float_as_uint(Psw[(r4    )*PPAD + 8*t + c4    ]);
            uint32_t a1 = __float_as_uint(Psw[(r4 + 8)*PPAD + 8*t + c4    ]);
            uint32_t a2 = __float_as_uint(Psw[(r4    )*PPAD + 8*t + c4 + 4]);
            uint32_t a3 = __float_as_uint(Psw[(r4 + 8)*PPAD + 8*t + c4 + 4]);
            #pragma unroll
            for (int j = 0; j < 16; j++) {
                float2 bb = *(const float2*)&Vt[(8*j + r4)*VTPAD + 8*t + 2*c4];
                mma8(o[j][0], o[j][1], o[j][2], o[j][3], a0, a1, a2, a3,
                     __float_as_uint(bb.x), __float_as_uint(bb.y));
            }
        }
        __syncthreads();
    }

    rs_lo += __shfl_xor_sync(0xffffffffu, rs_lo, 1);
    rs_lo += __shfl_xor_sync(0xffffffffu, rs_lo, 2);
    rs_hi += __shfl_xor_sync(0xffffffffu, rs_hi, 1);
    rs_hi += __shfl_xor_sync(0xffffffffu, rs_hi, 2);
    float inv_lo = 1.f / rs_lo;
    float inv_hi = 1.f / rs_hi;
    #pragma unroll
    for (int j = 0; j < 16; j++) {
        int d = 8*j + 2*c4;
        size_t blo = ((size_t)bh * NS + mlo) * ND + d;
        size_t bhi = ((size_t)bh * NS + mhi) * ND + d;
        *(float2*)&g_ctx[blo] = make_float2(o[j][0] * inv_lo, o[j][1] * inv_lo);
        *(float2*)&g_ctx[bhi] = make_float2(o[j][2] * inv_hi, o[j][3] * inv_hi);
    }
}

// ---------------------------------------------------------------------------
extern "C" void kernel_launch(void* const* d_in, const int* in_sizes, int n_in,
                              void* d_out, int out_size) {
    const float* x     = (const float*)d_in[0];
    const int*   edge  = (const int*)d_in[1];
    const float* W_in  = (const float*)d_in[2];
    const float* b_in  = (const float*)d_in[3];
    const float* W_out = (const float*)d_in[4];
    const float* b_out = (const float*)d_in[5];
    float* out = (float*)d_out;

    static const size_t attn_smem = ATTN_SMEM_FLOATS * sizeof(float);
    static const size_t proj_smem = PROJ_SMEM_FLOATS * sizeof(float);
    cudaFuncSetAttribute((const void*)attn_kernel,
                         cudaFuncAttributeMaxDynamicSharedMemorySize, (int)attn_smem);
    cudaFuncSetAttribute((const void*)qkv_kernel,
                         cudaFuncAttributeMaxDynamicSharedMemorySize, (int)proj_smem);
    cudaFuncSetAttribute((const void*)outproj_kernel,
                         cudaFuncAttributeMaxDynamicSharedMemorySize, (int)proj_smem);

    ln_stats_kernel<<<NB, 256>>>(x, edge);
    prep_kernel<<<78, 256>>>(edge, W_in, W_out);
    qkv_kernel<<<dim3(2, 128), 256, proj_smem>>>(x, b_in);
    attn_kernel<<<NB * NH * (NS / 128), 256, attn_smem>>>();
    outproj_kernel<<<dim3(4, 128), 256, proj_smem>>>(b_out, out);
}

// round 6
// speedup vs baseline: 1.3331x; 1.3331x over previous
#include <cuda_runtime.h>
#include <math.h>
#include <stdint.h>

#define NB 16
#define NS 1024
#define ND 128
#define NH 4
#define LNEPS 1e-5f

// Scratch (device globals: allocation-free per harness rules)
__device__ float g_q[NB*NH*NS*ND];        // [bh][s][d]
__device__ float g_k[NB*NH*NS*ND];        // [bh][s][d]
__device__ float g_v[NB*NH*NS*ND];        // [bh][s][d]
__device__ float g_kp[NB*NH*NS*ND];       // [bh][s][d_perm]   (pair-permuted d)
__device__ float g_vt[NB*NH*NS*ND];       // [bh][d][s_perm]   (d-major, pair-permuted s)
__device__ float g_ctx[NB*NH*NS*ND];
__device__ float g_win_perm[NH*3*ND*ND];  // W_in rows, pair-permuted k
__device__ float g_wout_perm[NH*ND*ND];   // W_out rows, pair-permuted k
__device__ float g_mean[NB];
__device__ float g_rstd[NB];
__device__ float g_wsum[NH*3*ND];
__device__ unsigned long long g_mbits[NH*NS*16];
__device__ int   g_edge64;

// pair-permutation within 8-groups: logical r -> slot (r<4 ? 2r : 2r-7)
__device__ __forceinline__ int slot8(int r) { return (r < 4) ? (r << 1) : ((r << 1) - 7); }
__device__ __forceinline__ int perm8(int idx) { return (idx & ~7) | slot8(idx & 7); }

__device__ __forceinline__ uint32_t f2tf(float f) {
    uint32_t r;
    asm("cvt.rna.tf32.f32 %0, %1;" : "=r"(r) : "f"(f));
    return r;
}

__device__ __forceinline__ void mma8(float& d0, float& d1, float& d2, float& d3,
                                     uint32_t a0, uint32_t a1, uint32_t a2, uint32_t a3,
                                     uint32_t b0, uint32_t b1) {
    asm volatile("mma.sync.aligned.m16n8k8.row.col.f32.tf32.tf32.f32 "
                 "{%0,%1,%2,%3}, {%4,%5,%6,%7}, {%8,%9}, {%0,%1,%2,%3};"
                 : "+f"(d0), "+f"(d1), "+f"(d2), "+f"(d3)
                 : "r"(a0), "r"(a1), "r"(a2), "r"(a3), "r"(b0), "r"(b1));
}

__device__ __forceinline__ void cp16(float* dst_smem, const float* src_gmem) {
    uint32_t d = (uint32_t)__cvta_generic_to_shared(dst_smem);
    asm volatile("cp.async.cg.shared.global [%0], [%1], 16;" :: "r"(d), "l"(src_gmem));
}

// ---------------------------------------------------------------------------
// K1: LayerNorm stats + edge dtype sniff
// ---------------------------------------------------------------------------
__global__ void ln_stats_kernel(const float* __restrict__ x,
                                const int* __restrict__ edge) {
    int b = blockIdx.x;
    const float4* xb = (const float4*)(x + (size_t)b * NS * ND);
    const int n4 = NS * ND / 4;
    float s = 0.f, ss = 0.f;
    for (int i = threadIdx.x; i < n4; i += blockDim.x) {
        float4 v = xb[i];
        s  += v.x + v.y + v.z + v.w;
        ss += v.x*v.x + v.y*v.y + v.z*v.z + v.w*v.w;
    }
    __shared__ float sh[256], sh2[256];
    sh[threadIdx.x] = s; sh2[threadIdx.x] = ss;
    __syncthreads();
    for (int o = 128; o > 0; o >>= 1) {
        if (threadIdx.x < o) {
            sh[threadIdx.x]  += sh[threadIdx.x + o];
            sh2[threadIdx.x] += sh2[threadIdx.x + o];
        }
        __syncthreads();
    }
    if (threadIdx.x == 0) {
        float inv_n = 1.f / (float)(NS * ND);
        float mu  = sh[0] * inv_n;
        float var = sh2[0] * inv_n - mu * mu;
        g_mean[b] = mu;
        g_rstd[b] = rsqrtf(var + LNEPS);
        if (b == 0) {
            int any = 0;
            #pragma unroll
            for (int i = 0; i < 64; i++) any |= edge[2*i + 1];
            g_edge64 = (any == 0) ? 1 : 0;
        }
    }
}

// ---------------------------------------------------------------------------
// K1b: prep — edge bitmasks, W column sums, pair-permuted weight copies
// ---------------------------------------------------------------------------
__global__ void prep_kernel(const int* __restrict__ edge,
                            const float* __restrict__ W_in,
                            const float* __restrict__ W_out) {
    int blk = blockIdx.x;
    if (blk < 64) {
        int idx = blk * 256 + threadIdx.x;
        int s = idx >> 4, t64 = idx & 15;
        unsigned long long m0 = 0, m1 = 0, m2 = 0, m3 = 0;
        if (g_edge64) {
            const int4* p = (const int4*)(edge + 2*((size_t)s*NS + t64*64));
            #pragma unroll
            for (int i = 0; i < 32; i++) {
                int4 v = p[i];
                unsigned long long b0 = 1ull << (2*i), b1 = 1ull << (2*i+1);
                if (v.x == 1) m0 |= b0;  if (v.z == 1) m0 |= b1;
                if (v.x == 2) m1 |= b0;  if (v.z == 2) m1 |= b1;
                if (v.x == 3) m2 |= b0;  if (v.z == 3) m2 |= b1;
                if (v.x == 4) m3 |= b0;  if (v.z == 4) m3 |= b1;
            }
        } else {
            const int4* p = (const int4*)(edge + ((size_t)s*NS + t64*64));
            #pragma unroll
            for (int i = 0; i < 16; i++) {
                int4 v = p[i];
                int e[4] = {v.x, v.y, v.z, v.w};
                #pragma unroll
                for (int q = 0; q < 4; q++) {
                    unsigned long long b = 1ull << (4*i + q);
                    if (e[q] == 1) m0 |= b;
                    if (e[q] == 2) m1 |= b;
                    if (e[q] == 3) m2 |= b;
                    if (e[q] == 4) m3 |= b;
                }
            }
        }
        g_mbits[(0*NS + s)*16 + t64] = m0;
        g_mbits[(1*NS + s)*16 + t64] = m1;
        g_mbits[(2*NS + s)*16 + t64] = m2;
        g_mbits[(3*NS + s)*16 + t64] = m3;
    } else if (blk < 70) {
        int col = (blk - 64) * 256 + threadIdx.x;
        float s = 0.f;
        const float4* p = (const float4*)(W_in + (size_t)col * ND);
        #pragma unroll
        for (int i = 0; i < 32; i++) {
            float4 v = p[i];
            s += v.x + v.y + v.z + v.w;
        }
        g_wsum[col] = s;
    } else {
        int row = (blk - 70) * 256 + threadIdx.x;   // 0..2047
        const float* src;
        float* dst;
        if (row < 1536) { src = W_in  + (size_t)row * ND;          dst = g_win_perm  + (size_t)row * ND; }
        else            { src = W_out + (size_t)(row - 1536) * ND; dst = g_wout_perm + (size_t)(row - 1536) * ND; }
        #pragma unroll
        for (int g = 0; g < 16; g++) {
            float4 lo = *(const float4*)&src[8*g];
            float4 hi = *(const float4*)&src[8*g + 4];
            *(float2*)&dst[8*g + 0] = make_float2(lo.x, hi.x);
            *(float2*)&dst[8*g + 2] = make_float2(lo.y, hi.y);
            *(float2*)&dst[8*g + 4] = make_float2(lo.z, hi.z);
            *(float2*)&dst[8*g + 6] = make_float2(lo.w, hi.w);
        }
    }
}

// ---------------------------------------------------------------------------
// K2b: reorder kernels — K pair-permute, V transpose(+key-permute)
// ---------------------------------------------------------------------------
__global__ void kperm_kernel() {
    int t = blockIdx.x * 256 + threadIdx.x;     // 0 .. 1048575
    int row = t >> 4;                           // (bh,s) row 0..65535
    int g = t & 15;                             // 8-group within d
    const float* src = g_k + (size_t)row * ND + 8*g;
    float* dst = g_kp + (size_t)row * ND + 8*g;
    float4 lo = *(const float4*)&src[0];
    float4 hi = *(const float4*)&src[4];
    *(float2*)&dst[0] = make_float2(lo.x, hi.x);
    *(float2*)&dst[2] = make_float2(lo.y, hi.y);
    *(float2*)&dst[4] = make_float2(lo.z, hi.z);
    *(float2*)&dst[6] = make_float2(lo.w, hi.w);
}

__global__ void vtrans_kernel() {
    __shared__ float tile[32][33];
    const int bh = blockIdx.x;
    const int s0 = blockIdx.y * 32;
    const int d0 = blockIdx.z * 32;
    const int tx = threadIdx.x & 31;
    const int ty = threadIdx.x >> 5;
    const float* src = g_v + (size_t)bh * NS * ND;
    float* dst = g_vt + (size_t)bh * ND * NS;
    #pragma unroll
    for (int i = 0; i < 4; i++) {
        int sy = ty + 8*i;
        tile[sy][tx] = src[(size_t)(s0 + sy) * ND + d0 + tx];
    }
    __syncthreads();
    const int sp = s0 + perm8(tx);
    #pragma unroll
    for (int i = 0; i < 4; i++) {
        int d = d0 + ty + 8*i;
        dst[(size_t)d * NS + sp] = tile[tx][ty + 8*i];
    }
}

// ---------------------------------------------------------------------------
// Projection kernels: tf32 mma; B pair-permuted -> conflict-free LDS.64 frags
// As pad 132 (scalar gather conflict-free), Bs pad 136 (paired conflict-free)
// ---------------------------------------------------------------------------
#define APJ 132
#define BPJ 136
#define PROJ_SMEM_FLOATS (128*APJ + 2*64*BPJ)

// K2: fused LN + QKV projection; R4-style vectorized epilogue
__global__ __launch_bounds__(256, 1) void qkv_kernel(const float* __restrict__ x,
                                                     const float* __restrict__ b_in) {
    extern __shared__ float sg[];
    float* As = sg;
    float* Bs0 = sg + 128*APJ;
    float* Bs1 = sg + 128*APJ + 64*BPJ;

    const int tid  = threadIdx.x;
    const int w    = tid >> 5;
    const int lane = tid & 31;
    const int r4   = lane >> 2;
    const int c4   = lane & 3;

    const int colbase = blockIdx.x * 768;
    const int m0 = blockIdx.y * 128;
    const int b  = blockIdx.y >> 3;
    const float mean = g_mean[b], rstd = g_rstd[b];
    const float mr = mean * rstd;

    #pragma unroll
    for (int i = 0; i < 16; i++) {
        int q = i * 256 + tid;
        int row = q >> 5, c = (q & 31) * 4;
        cp16(&As[row*APJ + c], &x[(size_t)(m0 + row) * ND + c]);
    }
    #pragma unroll
    for (int i = 0; i < 8; i++) {
        int q = i * 256 + tid;
        int row = q >> 5, c = (q & 31) * 4;
        cp16(&Bs0[row*BPJ + c], &g_win_perm[(size_t)(colbase + row) * ND + c]);
    }
    asm volatile("cp.async.commit_group;");
    asm volatile("cp.async.wait_group 0;");
    __syncthreads();

    uint32_t Af[64];
    {
        const int rl = 16*w + r4;
        #pragma unroll
        for (int t = 0; t < 16; t++) {
            Af[4*t+0] = f2tf(As[(rl    )*APJ + 8*t + c4    ]);
            Af[4*t+1] = f2tf(As[(rl + 8)*APJ + 8*t + c4    ]);
            Af[4*t+2] = f2tf(As[(rl    )*APJ + 8*t + c4 + 4]);
            Af[4*t+3] = f2tf(As[(rl + 8)*APJ + 8*t + c4 + 4]);
        }
    }

    const int rlo = m0 + 16*w + r4;
    const int rhi = rlo + 8;
    const int slo = rlo & (NS - 1);
    const int shi = rhi & (NS - 1);

    #define NTQ 12
    for (int nt = 0; nt < NTQ; nt++) {
        const int buf = nt & 1;
        float* Bcur = buf ? Bs1 : Bs0;
        float* Bnxt = buf ? Bs0 : Bs1;
        if (nt + 1 < NTQ) {
            const int nrow = colbase + (nt + 1) * 64;
            #pragma unroll
            for (int i = 0; i < 8; i++) {
                int q = i * 256 + tid;
                int row = q >> 5, c = (q & 31) * 4;
                cp16(&Bnxt[row*BPJ + c], &g_win_perm[(size_t)(nrow + row) * ND + c]);
            }
            asm volatile("cp.async.commit_group;");
        }

        float acc[8][4];
        #pragma unroll
        for (int j = 0; j < 8; j++)
            #pragma unroll
            for (int k = 0; k < 4; k++) acc[j][k] = 0.f;

        #pragma unroll
        for (int t = 0; t < 16; t++) {
            uint32_t a0 = Af[4*t], a1 = Af[4*t+1], a2 = Af[4*t+2], a3 = Af[4*t+3];
            #pragma unroll
            for (int j = 0; j < 8; j++) {
                float2 bb = *(const float2*)&Bcur[(8*j + r4)*BPJ + 8*t + 2*c4];
                mma8(acc[j][0], acc[j][1], acc[j][2], acc[j][3], a0, a1, a2, a3,
                     __float_as_uint(bb.x), __float_as_uint(bb.y));
            }
        }

        const int n0 = colbase + nt * 64;
        #pragma unroll
        for (int j = 0; j < 8; j++) {
            int colg = n0 + 8*j + 2*c4;
            float2 bias = *(const float2*)&b_in[colg];
            float2 ws   = *(const float2*)&g_wsum[colg];
            float off0 = bias.x - mr * ws.x;
            float off1 = bias.y - mr * ws.y;
            int hh = colg / 384;
            int r  = colg - hh * 384;
            int which = r >> 7;
            int d = r & 127;
            float* dst = (which == 0) ? g_q : (which == 1) ? g_k : g_v;
            size_t base = ((size_t)(b*NH + hh)) * NS * ND + d;
            *(float2*)&dst[base + (size_t)slo * ND] =
                make_float2(rstd*acc[j][0] + off0, rstd*acc[j][1] + off1);
            *(float2*)&dst[base + (size_t)shi * ND] =
                make_float2(rstd*acc[j][2] + off0, rstd*acc[j][3] + off1);
        }

        if (nt + 1 < NTQ) {
            asm volatile("cp.async.wait_group 0;");
            __syncthreads();
        }
    }
}

// K4: out projection
__global__ __launch_bounds__(256, 1) void outproj_kernel(const float* __restrict__ b_out,
                                                         float* __restrict__ out) {
    extern __shared__ float sg[];
    float* As = sg;
    float* Bs0 = sg + 128*APJ;
    float* Bs1 = sg + 128*APJ + 64*BPJ;

    const int tid  = threadIdx.x;
    const int w    = tid >> 5;
    const int lane = tid & 31;
    const int r4   = lane >> 2;
    const int c4   = lane & 3;

    const int hh = blockIdx.x;
    const int m0 = blockIdx.y * 128;
    const int b  = blockIdx.y >> 3;
    const int s0 = m0 & (NS - 1);
    const float* Ag = g_ctx + ((size_t)(b*NH + hh) * NS + s0) * ND;
    const int colbase = hh * 128;

    #pragma unroll
    for (int i = 0; i < 16; i++) {
        int q = i * 256 + tid;
        int row = q >> 5, c = (q & 31) * 4;
        cp16(&As[row*APJ + c], &Ag[(size_t)row * ND + c]);
    }
    #pragma unroll
    for (int i = 0; i < 8; i++) {
        int q = i * 256 + tid;
        int row = q >> 5, c = (q & 31) * 4;
        cp16(&Bs0[row*BPJ + c], &g_wout_perm[(size_t)(colbase + row) * ND + c]);
    }
    asm volatile("cp.async.commit_group;");
    asm volatile("cp.async.wait_group 0;");
    __syncthreads();

    uint32_t Af[64];
    {
        const int rl = 16*w + r4;
        #pragma unroll
        for (int t = 0; t < 16; t++) {
            Af[4*t+0] = f2tf(As[(rl    )*APJ + 8*t + c4    ]);
            Af[4*t+1] = f2tf(As[(rl + 8)*APJ + 8*t + c4    ]);
            Af[4*t+2] = f2tf(As[(rl    )*APJ + 8*t + c4 + 4]);
            Af[4*t+3] = f2tf(As[(rl + 8)*APJ + 8*t + c4 + 4]);
        }
    }

    const int rlo = m0 + 16*w + r4;
    const int rhi = rlo + 8;

    #pragma unroll
    for (int nt = 0; nt < 2; nt++) {
        float* Bcur = nt ? Bs1 : Bs0;
        float* Bnxt = nt ? Bs0 : Bs1;
        if (nt == 0) {
            const int nrow = colbase + 64;
            #pragma unroll
            for (int i = 0; i < 8; i++) {
                int q = i * 256 + tid;
                int row = q >> 5, c = (q & 31) * 4;
                cp16(&Bnxt[row*BPJ + c], &g_wout_perm[(size_t)(nrow + row) * ND + c]);
            }
            asm volatile("cp.async.commit_group;");
        }

        float acc[8][4];
        #pragma unroll
        for (int j = 0; j < 8; j++)
            #pragma unroll
            for (int k = 0; k < 4; k++) acc[j][k] = 0.f;

        #pragma unroll
        for (int t = 0; t < 16; t++) {
            uint32_t a0 = Af[4*t], a1 = Af[4*t+1], a2 = Af[4*t+2], a3 = Af[4*t+3];
            #pragma unroll
            for (int j = 0; j < 8; j++) {
                float2 bb = *(const float2*)&Bcur[(8*j + r4)*BPJ + 8*t + 2*c4];
                mma8(acc[j][0], acc[j][1], acc[j][2], acc[j][3], a0, a1, a2, a3,
                     __float_as_uint(bb.x), __float_as_uint(bb.y));
            }
        }

        const int n0 = colbase + nt * 64;
        #pragma unroll
        for (int j = 0; j < 8; j++) {
            int colg = n0 + 8*j + 2*c4;
            float2 bias = *(const float2*)&b_out[colg];
            *(float2*)&out[(size_t)rlo * (NH*ND) + colg] =
                make_float2(acc[j][0] + bias.x, acc[j][1] + bias.y);
            *(float2*)&out[(size_t)rhi * (NH*ND) + colg] =
                make_float2(acc[j][2] + bias.x, acc[j][3] + bias.y);
        }

        if (nt == 0) {
            asm volatile("cp.async.wait_group 0;");
            __syncthreads();
        }
    }
}

// ---------------------------------------------------------------------------
// K3: flash attention (tf32 mma, bitmask edges, no-max softmax,
//     conflict-free LDS.64 B-frags from g_kp / g_vt)
// ---------------------------------------------------------------------------
#define QPAD 132
#define KPAD 136
#define VTPAD 72
#define PPAD 68
#define OFF_K0 0
#define OFF_K1 (64*KPAD)
#define OFF_V0 (2*64*KPAD)
#define OFF_V1 (OFF_V0 + 128*VTPAD)
#define OFF_P  (OFF_V1 + 128*VTPAD)
#define OFF_QSTG OFF_V1
#define ATTN_SMEM_FLOATS (OFF_P + 128*PPAD)   // 44544 floats = 178176 B

__device__ __forceinline__ void load_kv_async(const float* __restrict__ Kgp,
                                              const float* __restrict__ Vgt,
                                              int n0, float* Ks, float* Vt, int tid) {
    #pragma unroll
    for (int i = 0; i < 8; i++) {
        int q = i * 256 + tid;
        int krow = q >> 5, kc = (q & 31) * 4;
        cp16(&Ks[krow*KPAD + kc], Kgp + (size_t)(n0 + krow) * ND + kc);
        int vrow = q >> 4, vc = (q & 15) * 4;
        cp16(&Vt[vrow*VTPAD + vc], Vgt + (size_t)vrow * NS + n0 + vc);
    }
}

__global__ __launch_bounds__(256, 1) void attn_kernel() {
    extern __shared__ float sm[];
    const int tid  = threadIdx.x;
    const int w    = tid >> 5;
    const int lane = tid & 31;
    const int r4   = lane >> 2;
    const int c4   = lane & 3;

    const int bh = blockIdx.x >> 3;
    const int qt = blockIdx.x & 7;
    const int h  = bh & 3;
    const int m0 = qt * 128;
    const float scale = 0.08838834764831845f;

    const float* Qg  = g_q  + (size_t)bh * NS * ND;
    const float* Kgp = g_kp + (size_t)bh * NS * ND;
    const float* Vgt = g_vt + (size_t)bh * ND * NS;   // d-major

    load_kv_async(Kgp, Vgt, 0, sm + OFF_K0, sm + OFF_V0, tid);
    asm volatile("cp.async.commit_group;");

    {
        float* Qstg = sm + OFF_QSTG;
        #pragma unroll
        for (int i = 0; i < 16; i++) {
            int q = i * 256 + tid;
            int row = q >> 5, cc = q & 31;
            *(float4*)&Qstg[row*QPAD + cc*4] =
                *(const float4*)&Qg[(size_t)(m0 + row) * ND + cc*4];
        }
    }
    __syncthreads();

    uint32_t Qf[64];
    {
        const float* Qstg = sm + OFF_QSTG;
        const int rl = 16*w + r4;
        #pragma unroll
        for (int t = 0; t < 16; t++) {
            Qf[4*t+0] = f2tf(Qstg[(rl    )*QPAD + 8*t + c4    ] * scale);
            Qf[4*t+1] = f2tf(Qstg[(rl + 8)*QPAD + 8*t + c4    ] * scale);
            Qf[4*t+2] = f2tf(Qstg[(rl    )*QPAD + 8*t + c4 + 4] * scale);
            Qf[4*t+3] = f2tf(Qstg[(rl + 8)*QPAD + 8*t + c4 + 4] * scale);
        }
    }
    __syncthreads();

    float o[16][4];
    #pragma unroll
    for (int j = 0; j < 16; j++)
        #pragma unroll
        for (int k = 0; k < 4; k++) o[j][k] = 0.f;
    float rs_lo = 0.f, rs_hi = 0.f;

    float* Psw = sm + OFF_P + w * 16 * PPAD;
    const int mlo = m0 + 16*w + r4;
    const int mhi = mlo + 8;
    const unsigned long long* mb_lo_base = &g_mbits[((size_t)h*NS + mlo)*16];
    const unsigned long long* mb_hi_base = &g_mbits[((size_t)h*NS + mhi)*16];

    for (int it = 0; it < 16; ++it) {
        const int buf = it & 1;
        if (it + 1 < 16) {
            load_kv_async(Kgp, Vgt, (it + 1) * 64,
                          sm + (buf ? OFF_K0 : OFF_K1),
                          sm + (buf ? OFF_V0 : OFF_V1), tid);
            asm volatile("cp.async.commit_group;");
            asm volatile("cp.async.wait_group 1;");
        } else {
            asm volatile("cp.async.wait_group 0;");
        }
        __syncthreads();

        const unsigned long long mb_lo = mb_lo_base[it];
        const unsigned long long mb_hi = mb_hi_base[it];

        const float* Ks = sm + (buf ? OFF_K1 : OFF_K0);
        const float* Vt = sm + (buf ? OFF_V1 : OFF_V0);

        // ---- QK^T (Q pre-scaled); K pair-permuted -> conflict-free LDS.64 ----
        float acc[8][4];
        #pragma unroll
        for (int j = 0; j < 8; j++)
            #pragma unroll
            for (int k = 0; k < 4; k++) acc[j][k] = 0.f;

        #pragma unroll
        for (int t = 0; t < 16; t++) {
            uint32_t a0 = Qf[4*t], a1 = Qf[4*t+1], a2 = Qf[4*t+2], a3 = Qf[4*t+3];
            #pragma unroll
            for (int j = 0; j < 8; j++) {
                float2 bb = *(const float2*)&Ks[(8*j + r4)*KPAD + 8*t + 2*c4];
                mma8(acc[j][0], acc[j][1], acc[j][2], acc[j][3], a0, a1, a2, a3,
                     __float_as_uint(bb.x), __float_as_uint(bb.y));
            }
        }

        // ---- exp + mask-select + P store ----
        #pragma unroll
        for (int j = 0; j < 8; j++) {
            unsigned blo = (unsigned)(mb_lo >> (8*j + 2*c4));
            unsigned bhi = (unsigned)(mb_hi >> (8*j + 2*c4));
            float p0 = (blo & 1u) ? __expf(acc[j][0]) : 0.f;
            float p1 = (blo & 2u) ? __expf(acc[j][1]) : 0.f;
            float p2 = (bhi & 1u) ? __expf(acc[j][2]) : 0.f;
            float p3 = (bhi & 2u) ? __expf(acc[j][3]) : 0.f;
            rs_lo += p0 + p1;
            rs_hi += p2 + p3;
            uint32_t u0 = f2tf(p0), u1 = f2tf(p1), u2 = f2tf(p2), u3 = f2tf(p3);
            *(uint2*)&Psw[(r4    )*PPAD + 8*j + 2*c4] = make_uint2(u0, u1);
            *(uint2*)&Psw[(r4 + 8)*PPAD + 8*j + 2*c4] = make_uint2(u2, u3);
        }
        __syncwarp();

        // ---- O += P @ V ; V d-major, key-permuted -> conflict-free LDS.64 ----
        #pragma unroll
        for (int t = 0; t < 8; t++) {
            uint32_t a0 = __float_as_uint(Psw[(r4    )*PPAD + 8*t + c4    ]);
            uint32_t a1 = __float_as_uint(Psw[(r4 + 8)*PPAD + 8*t + c4    ]);
            uint32_t a2 = __float_as_uint(Psw[(r4    )*PPAD + 8*t + c4 + 4]);
            uint32_t a3 = __float_as_uint(Psw[(r4 + 8)*PPAD + 8*t + c4 + 4]);
            #pragma unroll
            for (int j = 0; j < 16; j++) {
                float2 bb = *(const float2*)&Vt[(8*j + r4)*VTPAD + 8*t + 2*c4];
                mma8(o[j][0], o[j][1], o[j][2], o[j][3], a0, a1, a2, a3,
                     __float_as_uint(bb.x), __float_as_uint(bb.y));
            }
        }
        __syncthreads();
    }

    rs_lo += __shfl_xor_sync(0xffffffffu, rs_lo, 1);
    rs_lo += __shfl_xor_sync(0xffffffffu, rs_lo, 2);
    rs_hi += __shfl_xor_sync(0xffffffffu, rs_hi, 1);
    rs_hi += __shfl_xor_sync(0xffffffffu, rs_hi, 2);
    float inv_lo = 1.f / rs_lo;
    float inv_hi = 1.f / rs_hi;
    #pragma unroll
    for (int j = 0; j < 16; j++) {
        int d = 8*j + 2*c4;
        size_t blo = ((size_t)bh * NS + mlo) * ND + d;
        size_t bhi = ((size_t)bh * NS + mhi) * ND + d;
        *(float2*)&g_ctx[blo] = make_float2(o[j][0] * inv_lo, o[j][1] * inv_lo);
        *(float2*)&g_ctx[bhi] = make_float2(o[j][2] * inv_hi, o[j][3] * inv_hi);
    }
}

// ---------------------------------------------------------------------------
extern "C" void kernel_launch(void* const* d_in, const int* in_sizes, int n_in,
                              void* d_out, int out_size) {
    const float* x     = (const float*)d_in[0];
    const int*   edge  = (const int*)d_in[1];
    const float* W_in  = (const float*)d_in[2];
    const float* b_in  = (const float*)d_in[3];
    const float* W_out = (const float*)d_in[4];
    const float* b_out = (const float*)d_in[5];
    float* out = (float*)d_out;

    static const size_t attn_smem = ATTN_SMEM_FLOATS * sizeof(float);
    static const size_t proj_smem = PROJ_SMEM_FLOATS * sizeof(float);
    cudaFuncSetAttribute((const void*)attn_kernel,
                         cudaFuncAttributeMaxDynamicSharedMemorySize, (int)attn_smem);
    cudaFuncSetAttribute((const void*)qkv_kernel,
                         cudaFuncAttributeMaxDynamicSharedMemorySize, (int)proj_smem);
    cudaFuncSetAttribute((const void*)outproj_kernel,
                         cudaFuncAttributeMaxDynamicSharedMemorySize, (int)proj_smem);

    ln_stats_kernel<<<NB, 256>>>(x, edge);
    prep_kernel<<<78, 256>>>(edge, W_in, W_out);
    qkv_kernel<<<dim3(2, 128), 256, proj_smem>>>(x, b_in);
    kperm_kernel<<<4096, 256>>>();
    vtrans_kernel<<<dim3(NB*NH, NS/32, ND/32), 256>>>();
    attn_kernel<<<NB * NH * (NS / 128), 256, attn_smem>>>();
    outproj_kernel<<<dim3(4, 128), 256, proj_smem>>>(b_out, out);
}

// round 8
// speedup vs baseline: 1.8600x; 1.3953x over previous
#include <cuda_runtime.h>
#include <cuda_fp16.h>
#include <math.h>
#include <stdint.h>

#define NB 16
#define NS 1024
#define ND 128
#define NH 4
#define LNEPS 1e-5f
#define SCALE 0.08838834764831845f

// Scratch (device globals: allocation-free per harness rules)
__device__ __half g_qh[NB*NH*NS*ND];       // [bh][s][d], scale folded, fp16
__device__ __half g_kh[NB*NH*NS*ND];       // [bh][s][d_slot16], fp16
__device__ float  g_v[NB*NH*NS*ND];        // [bh][s][d], f32 (vtrans input)
__device__ __half g_vth[NB*NH*NS*ND];      // [bh][d][s_slot16], fp16
__device__ float  g_ctx[NB*NH*NS*ND];
__device__ float  g_win_perm[NH*3*ND*ND];  // W_in rows, pair-permuted k (tf32 proj)
__device__ float  g_wout_perm[NH*ND*ND];
__device__ float  g_mean[NB];
__device__ float  g_rstd[NB];
__device__ float  g_wsum[NH*3*ND];
__device__ unsigned long long g_mbits[NH*NS*16];
__device__ int    g_edge64;

// slot16: within each 16-group, order 0,1,8,9,2,3,10,11,4,5,12,13,6,7,14,15
__device__ __forceinline__ int slot16(int k) {
    return (k < 8) ? ((k >> 1) * 4 + (k & 1)) : (((k - 8) >> 1) * 4 + 2 + (k & 1));
}

__device__ __forceinline__ uint32_t f2tf(float f) {
    uint32_t r;
    asm("cvt.rna.tf32.f32 %0, %1;" : "=r"(r) : "f"(f));
    return r;
}

__device__ __forceinline__ void mma8(float& d0, float& d1, float& d2, float& d3,
                                     uint32_t a0, uint32_t a1, uint32_t a2, uint32_t a3,
                                     uint32_t b0, uint32_t b1) {
    asm volatile("mma.sync.aligned.m16n8k8.row.col.f32.tf32.tf32.f32 "
                 "{%0,%1,%2,%3}, {%4,%5,%6,%7}, {%8,%9}, {%0,%1,%2,%3};"
                 : "+f"(d0), "+f"(d1), "+f"(d2), "+f"(d3)
                 : "r"(a0), "r"(a1), "r"(a2), "r"(a3), "r"(b0), "r"(b1));
}

__device__ __forceinline__ void mma16(float& d0, float& d1, float& d2, float& d3,
                                      uint32_t a0, uint32_t a1, uint32_t a2, uint32_t a3,
                                      uint32_t b0, uint32_t b1) {
    asm volatile("mma.sync.aligned.m16n8k16.row.col.f32.f16.f16.f32 "
                 "{%0,%1,%2,%3}, {%4,%5,%6,%7}, {%8,%9}, {%0,%1,%2,%3};"
                 : "+f"(d0), "+f"(d1), "+f"(d2), "+f"(d3)
                 : "r"(a0), "r"(a1), "r"(a2), "r"(a3), "r"(b0), "r"(b1));
}

__device__ __forceinline__ void cp16(void* dst_smem, const void* src_gmem) {
    uint32_t d = (uint32_t)__cvta_generic_to_shared(dst_smem);
    asm volatile("cp.async.cg.shared.global [%0], [%1], 16;" :: "r"(d), "l"(src_gmem));
}

// ---------------------------------------------------------------------------
// K1: LayerNorm stats + edge dtype sniff
// ---------------------------------------------------------------------------
__global__ void ln_stats_kernel(const float* __restrict__ x,
                                const int* __restrict__ edge) {
    int b = blockIdx.x;
    const float4* xb = (const float4*)(x + (size_t)b * NS * ND);
    const int n4 = NS * ND / 4;
    float s = 0.f, ss = 0.f;
    for (int i = threadIdx.x; i < n4; i += blockDim.x) {
        float4 v = xb[i];
        s  += v.x + v.y + v.z + v.w;
        ss += v.x*v.x + v.y*v.y + v.z*v.z + v.w*v.w;
    }
    __shared__ float sh[256], sh2[256];
    sh[threadIdx.x] = s; sh2[threadIdx.x] = ss;
    __syncthreads();
    for (int o = 128; o > 0; o >>= 1) {
        if (threadIdx.x < o) {
            sh[threadIdx.x]  += sh[threadIdx.x + o];
            sh2[threadIdx.x] += sh2[threadIdx.x + o];
        }
        __syncthreads();
    }
    if (threadIdx.x == 0) {
        float inv_n = 1.f / (float)(NS * ND);
        float mu  = sh[0] * inv_n;
        float var = sh2[0] * inv_n - mu * mu;
        g_mean[b] = mu;
        g_rstd[b] = rsqrtf(var + LNEPS);
        if (b == 0) {
            int any = 0;
            #pragma unroll
            for (int i = 0; i < 64; i++) any |= edge[2*i + 1];
            g_edge64 = (any == 0) ? 1 : 0;
        }
    }
}

// ---------------------------------------------------------------------------
// K1b: prep — edge bitmasks, W column sums, pair-permuted weight copies
// ---------------------------------------------------------------------------
__global__ void prep_kernel(const int* __restrict__ edge,
                            const float* __restrict__ W_in,
                            const float* __restrict__ W_out) {
    int blk = blockIdx.x;
    if (blk < 64) {
        int idx = blk * 256 + threadIdx.x;
        int s = idx >> 4, t64 = idx & 15;
        unsigned long long m0 = 0, m1 = 0, m2 = 0, m3 = 0;
        if (g_edge64) {
            const int4* p = (const int4*)(edge + 2*((size_t)s*NS + t64*64));
            #pragma unroll
            for (int i = 0; i < 32; i++) {
                int4 v = p[i];
                unsigned long long b0 = 1ull << (2*i), b1 = 1ull << (2*i+1);
                if (v.x == 1) m0 |= b0;  if (v.z == 1) m0 |= b1;
                if (v.x == 2) m1 |= b0;  if (v.z == 2) m1 |= b1;
                if (v.x == 3) m2 |= b0;  if (v.z == 3) m2 |= b1;
                if (v.x == 4) m3 |= b0;  if (v.z == 4) m3 |= b1;
            }
        } else {
            const int4* p = (const int4*)(edge + ((size_t)s*NS + t64*64));
            #pragma unroll
            for (int i = 0; i < 16; i++) {
                int4 v = p[i];
                int e[4] = {v.x, v.y, v.z, v.w};
                #pragma unroll
                for (int q = 0; q < 4; q++) {
                    unsigned long long b = 1ull << (4*i + q);
                    if (e[q] == 1) m0 |= b;
                    if (e[q] == 2) m1 |= b;
                    if (e[q] == 3) m2 |= b;
                    if (e[q] == 4) m3 |= b;
                }
            }
        }
        g_mbits[(0*NS + s)*16 + t64] = m0;
        g_mbits[(1*NS + s)*16 + t64] = m1;
        g_mbits[(2*NS + s)*16 + t64] = m2;
        g_mbits[(3*NS + s)*16 + t64] = m3;
    } else if (blk < 70) {
        int col = (blk - 64) * 256 + threadIdx.x;
        float s = 0.f;
        const float4* p = (const float4*)(W_in + (size_t)col * ND);
        #pragma unroll
        for (int i = 0; i < 32; i++) {
            float4 v = p[i];
            s += v.x + v.y + v.z + v.w;
        }
        g_wsum[col] = s;
    } else {
        int row = (blk - 70) * 256 + threadIdx.x;   // 0..2047
        const float* src;
        float* dst;
        if (row < 1536) { src = W_in  + (size_t)row * ND;          dst = g_win_perm  + (size_t)row * ND; }
        else            { src = W_out + (size_t)(row - 1536) * ND; dst = g_wout_perm + (size_t)(row - 1536) * ND; }
        #pragma unroll
        for (int g = 0; g < 16; g++) {
            float4 lo = *(const float4*)&src[8*g];
            float4 hi = *(const float4*)&src[8*g + 4];
            *(float2*)&dst[8*g + 0] = make_float2(lo.x, hi.x);
            *(float2*)&dst[8*g + 2] = make_float2(lo.y, hi.y);
            *(float2*)&dst[8*g + 4] = make_float2(lo.z, hi.z);
            *(float2*)&dst[8*g + 6] = make_float2(lo.w, hi.w);
        }
    }
}

// ---------------------------------------------------------------------------
// K2b: V transpose f32 -> f16, d-major, slot16-interleaved s
// ---------------------------------------------------------------------------
__global__ void vtrans_kernel() {
    __shared__ float tile[32][33];
    const int bh = blockIdx.x;
    const int s0 = blockIdx.y * 32;
    const int d0 = blockIdx.z * 32;
    const int tx = threadIdx.x & 31;
    const int ty = threadIdx.x >> 5;
    const float* src = g_v + (size_t)bh * NS * ND;
    __half* dst = g_vth + (size_t)bh * ND * NS;
    #pragma unroll
    for (int i = 0; i < 4; i++) {
        int sy = ty + 8*i;
        tile[sy][tx] = src[(size_t)(s0 + sy) * ND + d0 + tx];
    }
    __syncthreads();
    const int sp = s0 + (tx & 16) + slot16(tx & 15);
    #pragma unroll
    for (int i = 0; i < 4; i++) {
        int d = d0 + ty + 8*i;
        dst[(size_t)d * NS + sp] = __float2half_rn(tile[tx][ty + 8*i]);
    }
}

// ---------------------------------------------------------------------------
// Projection kernels: tf32 mma; B pair-permuted -> conflict-free LDS.64 frags
// ---------------------------------------------------------------------------
#define APJ 132
#define BPJ 136
#define PROJ_SMEM_FLOATS (128*APJ + 2*64*BPJ)

// K2: fused LN + QKV projection; writes q/k as fp16 (q scaled, k slot16), v f32
__global__ __launch_bounds__(256, 1) void qkv_kernel(const float* __restrict__ x,
                                                     const float* __restrict__ b_in) {
    extern __shared__ float sg[];
    float* As = sg;
    float* Bs0 = sg + 128*APJ;
    float* Bs1 = sg + 128*APJ + 64*BPJ;

    const int tid  = threadIdx.x;
    const int w    = tid >> 5;
    const int lane = tid & 31;
    const int r4   = lane >> 2;
    const int c4   = lane & 3;

    const int colbase = blockIdx.x * 768;
    const int m0 = blockIdx.y * 128;
    const int b  = blockIdx.y >> 3;
    const float mean = g_mean[b], rstd = g_rstd[b];
    const float mr = mean * rstd;

    #pragma unroll
    for (int i = 0; i < 16; i++) {
        int q = i * 256 + tid;
        int row = q >> 5, c = (q & 31) * 4;
        cp16(&As[row*APJ + c], &x[(size_t)(m0 + row) * ND + c]);
    }
    #pragma unroll
    for (int i = 0; i < 8; i++) {
        int q = i * 256 + tid;
        int row = q >> 5, c = (q & 31) * 4;
        cp16(&Bs0[row*BPJ + c], &g_win_perm[(size_t)(colbase + row) * ND + c]);
    }
    asm volatile("cp.async.commit_group;");
    asm volatile("cp.async.wait_group 0;");
    __syncthreads();

    uint32_t Af[64];
    {
        const int rl = 16*w + r4;
        #pragma unroll
        for (int t = 0; t < 16; t++) {
            Af[4*t+0] = f2tf(As[(rl    )*APJ + 8*t + c4    ]);
            Af[4*t+1] = f2tf(As[(rl + 8)*APJ + 8*t + c4    ]);
            Af[4*t+2] = f2tf(As[(rl    )*APJ + 8*t + c4 + 4]);
            Af[4*t+3] = f2tf(As[(rl + 8)*APJ + 8*t + c4 + 4]);
        }
    }

    const int rlo = m0 + 16*w + r4;
    const int rhi = rlo + 8;
    const int slo = rlo & (NS - 1);
    const int shi = rhi & (NS - 1);

    #define NTQ 12
    for (int nt = 0; nt < NTQ; nt++) {
        const int buf = nt & 1;
        float* Bcur = buf ? Bs1 : Bs0;
        float* Bnxt = buf ? Bs0 : Bs1;
        if (nt + 1 < NTQ) {
            const int nrow = colbase + (nt + 1) * 64;
            #pragma unroll
            for (int i = 0; i < 8; i++) {
                int q = i * 256 + tid;
                int row = q >> 5, c = (q & 31) * 4;
                cp16(&Bnxt[row*BPJ + c], &g_win_perm[(size_t)(nrow + row) * ND + c]);
            }
            asm volatile("cp.async.commit_group;");
        }

        float acc[8][4];
        #pragma unroll
        for (int j = 0; j < 8; j++)
            #pragma unroll
            for (int k = 0; k < 4; k++) acc[j][k] = 0.f;

        #pragma unroll
        for (int t = 0; t < 16; t++) {
            uint32_t a0 = Af[4*t], a1 = Af[4*t+1], a2 = Af[4*t+2], a3 = Af[4*t+3];
            #pragma unroll
            for (int j = 0; j < 8; j++) {
                float2 bb = *(const float2*)&Bcur[(8*j + r4)*BPJ + 8*t + 2*c4];
                mma8(acc[j][0], acc[j][1], acc[j][2], acc[j][3], a0, a1, a2, a3,
                     __float_as_uint(bb.x), __float_as_uint(bb.y));
            }
        }

        const int n0 = colbase + nt * 64;
        #pragma unroll
        for (int j = 0; j < 8; j++) {
            int colg = n0 + 8*j + 2*c4;
            float2 bias = *(const float2*)&b_in[colg];
            float2 ws   = *(const float2*)&g_wsum[colg];
            float off0 = bias.x - mr * ws.x;
            float off1 = bias.y - mr * ws.y;
            float v00 = rstd*acc[j][0] + off0, v01 = rstd*acc[j][1] + off1;
            float v10 = rstd*acc[j][2] + off0, v11 = rstd*acc[j][3] + off1;
            int hh = colg / 384;
            int r  = colg - hh * 384;
            int which = r >> 7;
            int d = r & 127;
            size_t base = ((size_t)(b*NH + hh)) * NS * ND;
            if (which == 0) {
                *(__half2*)&g_qh[base + (size_t)slo * ND + d] =
                    __floats2half2_rn(v00 * SCALE, v01 * SCALE);
                *(__half2*)&g_qh[base + (size_t)shi * ND + d] =
                    __floats2half2_rn(v10 * SCALE, v11 * SCALE);
            } else if (which == 1) {
                int dl = d & 15;
                int sb = (dl < 8) ? (dl * 2) : ((dl - 8) * 2 + 2);
                int dp = (d & ~15) | sb;
                *(__half2*)&g_kh[base + (size_t)slo * ND + dp] = __floats2half2_rn(v00, v01);
                *(__half2*)&g_kh[base + (size_t)shi * ND + dp] = __floats2half2_rn(v10, v11);
            } else {
                *(float2*)&g_v[base + (size_t)slo * ND + d] = make_float2(v00, v01);
                *(float2*)&g_v[base + (size_t)shi * ND + d] = make_float2(v10, v11);
            }
        }

        if (nt + 1 < NTQ) {
            asm volatile("cp.async.wait_group 0;");
            __syncthreads();
        }
    }
}

// K4: out projection
__global__ __launch_bounds__(256, 1) void outproj_kernel(const float* __restrict__ b_out,
                                                         float* __restrict__ out) {
    extern __shared__ float sg[];
    float* As = sg;
    float* Bs0 = sg + 128*APJ;
    float* Bs1 = sg + 128*APJ + 64*BPJ;

    const int tid  = threadIdx.x;
    const int w    = tid >> 5;
    const int lane = tid & 31;
    const int r4   = lane >> 2;
    const int c4   = lane & 3;

    const int hh = blockIdx.x;
    const int m0 = blockIdx.y * 128;
    const int b  = blockIdx.y >> 3;
    const int s0 = m0 & (NS - 1);
    const float* Ag = g_ctx + ((size_t)(b*NH + hh) * NS + s0) * ND;
    const int colbase = hh * 128;

    #pragma unroll
    for (int i = 0; i < 16; i++) {
        int q = i * 256 + tid;
        int row = q >> 5, c = (q & 31) * 4;
        cp16(&As[row*APJ + c], &Ag[(size_t)row * ND + c]);
    }
    #pragma unroll
    for (int i = 0; i < 8; i++) {
        int q = i * 256 + tid;
        int row = q >> 5, c = (q & 31) * 4;
        cp16(&Bs0[row*BPJ + c], &g_wout_perm[(size_t)(colbase + row) * ND + c]);
    }
    asm volatile("cp.async.commit_group;");
    asm volatile("cp.async.wait_group 0;");
    __syncthreads();

    uint32_t Af[64];
    {
        const int rl = 16*w + r4;
        #pragma unroll
        for (int t = 0; t < 16; t++) {
            Af[4*t+0] = f2tf(As[(rl    )*APJ + 8*t + c4    ]);
            Af[4*t+1] = f2tf(As[(rl + 8)*APJ + 8*t + c4    ]);
            Af[4*t+2] = f2tf(As[(rl    )*APJ + 8*t + c4 + 4]);
            Af[4*t+3] = f2tf(As[(rl + 8)*APJ + 8*t + c4 + 4]);
        }
    }

    const int rlo = m0 + 16*w + r4;
    const int rhi = rlo + 8;

    #pragma unroll
    for (int nt = 0; nt < 2; nt++) {
        float* Bcur = nt ? Bs1 : Bs0;
        float* Bnxt = nt ? Bs0 : Bs1;
        if (nt == 0) {
            const int nrow = colbase + 64;
            #pragma unroll
            for (int i = 0; i < 8; i++) {
                int q = i * 256 + tid;
                int row = q >> 5, c = (q & 31) * 4;
                cp16(&Bnxt[row*BPJ + c], &g_wout_perm[(size_t)(nrow + row) * ND + c]);
            }
            asm volatile("cp.async.commit_group;");
        }

        float acc[8][4];
        #pragma unroll
        for (int j = 0; j < 8; j++)
            #pragma unroll
            for (int k = 0; k < 4; k++) acc[j][k] = 0.f;

        #pragma unroll
        for (int t = 0; t < 16; t++) {
            uint32_t a0 = Af[4*t], a1 = Af[4*t+1], a2 = Af[4*t+2], a3 = Af[4*t+3];
            #pragma unroll
            for (int j = 0; j < 8; j++) {
                float2 bb = *(const float2*)&Bcur[(8*j + r4)*BPJ + 8*t + 2*c4];
                mma8(acc[j][0], acc[j][1], acc[j][2], acc[j][3], a0, a1, a2, a3,
                     __float_as_uint(bb.x), __float_as_uint(bb.y));
            }
        }

        const int n0 = colbase + nt * 64;
        #pragma unroll
        for (int j = 0; j < 8; j++) {
            int colg = n0 + 8*j + 2*c4;
            float2 bias = *(const float2*)&b_out[colg];
            *(float2*)&out[(size_t)rlo * (NH*ND) + colg] =
                make_float2(acc[j][0] + bias.x, acc[j][1] + bias.y);
            *(float2*)&out[(size_t)rhi * (NH*ND) + colg] =
                make_float2(acc[j][2] + bias.x, acc[j][3] + bias.y);
        }

        if (nt == 0) {
            asm volatile("cp.async.wait_group 0;");
            __syncthreads();
        }
    }
}

// ---------------------------------------------------------------------------
// K3: flash attention, fp16 mma.m16n8k16, 4-slot cp.async pipeline,
//     bitmask edges, no-max softmax, slot16 LDS.64 operands.
// ---------------------------------------------------------------------------
#define KPH 144     // K tile row stride (halves): 288B -> CF LDS.64
#define VPH 80      // V^T row stride (halves): 160B -> CF
#define PPH 80      // P row stride (halves)
#define QSH 136     // Q staging row stride (halves)
#define OFF_K   0
#define OFF_V   (4*64*KPH)                  // 36864
#define OFF_P   (OFF_V + 4*128*VPH)         // 77824
#define OFF_QSTG (OFF_V + 128*VPH)          // 47104 (overlaps V slots 1-2)
#define ATTN_SMEM_HALVES (OFF_P + 128*PPH)  // 88064 halves = 176128 B

__device__ __forceinline__ void load_kv_async(const __half* __restrict__ Kg,
                                              const __half* __restrict__ Vg,
                                              int n0, __half* Ks, __half* Vt, int tid) {
    #pragma unroll
    for (int i = 0; i < 4; i++) {
        int q = i * 256 + tid;
        int kr = q >> 4, kc = (q & 15) * 8;
        cp16(&Ks[kr*KPH + kc], Kg + (size_t)(n0 + kr) * ND + kc);
        int vr = q >> 3, vc = (q & 7) * 8;
        cp16(&Vt[vr*VPH + vc], Vg + (size_t)vr * NS + n0 + vc);
    }
}

__global__ __launch_bounds__(256, 1) void attn_kernel() {
    extern __shared__ __half smh[];
    const int tid  = threadIdx.x;
    const int w    = tid >> 5;
    const int lane = tid & 31;
    const int r4   = lane >> 2;
    const int c4   = lane & 3;

    const int bh = blockIdx.x >> 3;
    const int qt = blockIdx.x & 7;
    const int h  = bh & 3;
    const int m0 = qt * 128;

    const __half* Qg = g_qh  + (size_t)bh * NS * ND;
    const __half* Kg = g_kh  + (size_t)bh * NS * ND;
    const __half* Vg = g_vth + (size_t)bh * ND * NS;

    // tile 0 into slot 0
    load_kv_async(Kg, Vg, 0, smh + OFF_K, smh + OFF_V, tid);
    asm volatile("cp.async.commit_group;");

    // stage Q: 128 rows x 128 halves; 2048 uint4 stores of 8 halves each
    // (FIX vs R7: row = q>>4, ch = (q&15)*8 — covers ALL 16 8-half chunks/row)
    {
        __half* Qstg = smh + OFF_QSTG;
        #pragma unroll
        for (int i = 0; i < 8; i++) {
            int q = i * 256 + tid;
            int row = q >> 4, ch = (q & 15) * 8;
            *(uint4*)&Qstg[row*QSH + ch] =
                *(const uint4*)&Qg[(size_t)(m0 + row) * ND + ch];
        }
    }
    __syncthreads();

    // gather Q A-fragments (fp16, scale already folded at qkv)
    uint32_t Qf[32];
    {
        const __half* Qstg = smh + OFF_QSTG;
        const int rl = 16*w + r4;
        #pragma unroll
        for (int t = 0; t < 8; t++) {
            Qf[4*t+0] = *(const uint32_t*)&Qstg[(rl    )*QSH + 16*t + 2*c4    ];
            Qf[4*t+1] = *(const uint32_t*)&Qstg[(rl + 8)*QSH + 16*t + 2*c4    ];
            Qf[4*t+2] = *(const uint32_t*)&Qstg[(rl    )*QSH + 16*t + 2*c4 + 8];
            Qf[4*t+3] = *(const uint32_t*)&Qstg[(rl + 8)*QSH + 16*t + 2*c4 + 8];
        }
    }
    __syncthreads();

    // tiles 1,2 into slots 1,2 (now safe: Q fragments gathered)
    load_kv_async(Kg, Vg, 64,  smh + OFF_K + 1*64*KPH, smh + OFF_V + 1*128*VPH, tid);
    asm volatile("cp.async.commit_group;");
    load_kv_async(Kg, Vg, 128, smh + OFF_K + 2*64*KPH, smh + OFF_V + 2*128*VPH, tid);
    asm volatile("cp.async.commit_group;");

    float o[16][4];
    #pragma unroll
    for (int j = 0; j < 16; j++)
        #pragma unroll
        for (int k = 0; k < 4; k++) o[j][k] = 0.f;
    float rs_lo = 0.f, rs_hi = 0.f;

    __half* Psw = smh + OFF_P + (w * 16) * PPH;
    const int mlo = m0 + 16*w + r4;
    const int mhi = mlo + 8;
    const unsigned long long* mb_lo_base = &g_mbits[((size_t)h*NS + mlo)*16];
    const unsigned long long* mb_hi_base = &g_mbits[((size_t)h*NS + mhi)*16];

    for (int it = 0; it < 16; ++it) {
        if (it < 14)       { asm volatile("cp.async.wait_group 2;"); }
        else if (it == 14) { asm volatile("cp.async.wait_group 1;"); }
        else               { asm volatile("cp.async.wait_group 0;"); }
        __syncthreads();
        if (it + 3 < 16) {
            int nslot = (it + 3) & 3;
            load_kv_async(Kg, Vg, (it + 3) * 64,
                          smh + OFF_K + nslot*64*KPH,
                          smh + OFF_V + nslot*128*VPH, tid);
            asm volatile("cp.async.commit_group;");
        }

        const __half* Ks = smh + OFF_K + (it & 3) * 64 * KPH;
        const __half* Vt = smh + OFF_V + (it & 3) * 128 * VPH;
        const unsigned long long mb_lo = mb_lo_base[it];
        const unsigned long long mb_hi = mb_hi_base[it];

        // ---- QK^T: 8 k-steps x 8 n-tiles, K slot16 -> one LDS.64 per B ----
        float acc[8][4];
        #pragma unroll
        for (int j = 0; j < 8; j++)
            #pragma unroll
            for (int k = 0; k < 4; k++) acc[j][k] = 0.f;

        #pragma unroll
        for (int t = 0; t < 8; t++) {
            uint32_t a0 = Qf[4*t], a1 = Qf[4*t+1], a2 = Qf[4*t+2], a3 = Qf[4*t+3];
            #pragma unroll
            for (int j = 0; j < 8; j++) {
                uint2 bb = *(const uint2*)&Ks[(8*j + r4)*KPH + 16*t + 4*c4];
                mma16(acc[j][0], acc[j][1], acc[j][2], acc[j][3],
                      a0, a1, a2, a3, bb.x, bb.y);
            }
        }

        // ---- exp + mask + P store (half2, slot16 along keys) ----
        #pragma unroll
        for (int j = 0; j < 8; j++) {
            unsigned blo = (unsigned)(mb_lo >> (8*j + 2*c4));
            unsigned bhi = (unsigned)(mb_hi >> (8*j + 2*c4));
            float p0 = (blo & 1u) ? __expf(acc[j][0]) : 0.f;
            float p1 = (blo & 2u) ? __expf(acc[j][1]) : 0.f;
            float p2 = (bhi & 1u) ? __expf(acc[j][2]) : 0.f;
            float p3 = (bhi & 2u) ? __expf(acc[j][3]) : 0.f;
            __half2 hlo = __floats2half2_rn(p0, p1);
            __half2 hhi = __floats2half2_rn(p2, p3);
            float2 flo = __half22float2(hlo);
            float2 fhi = __half22float2(hhi);
            rs_lo += flo.x + flo.y;
            rs_hi += fhi.x + fhi.y;
            int off = (j >> 1) * 16 + 4*c4 + 2*(j & 1);
            *(__half2*)&Psw[(r4    )*PPH + off] = hlo;
            *(__half2*)&Psw[(r4 + 8)*PPH + off] = hhi;
        }
        __syncwarp();

        // ---- O += P @ V : 4 k-steps x 16 d-tiles ----
        #pragma unroll
        for (int t = 0; t < 4; t++) {
            uint2 aLo = *(const uint2*)&Psw[(r4    )*PPH + 16*t + 4*c4];
            uint2 aHi = *(const uint2*)&Psw[(r4 + 8)*PPH + 16*t + 4*c4];
            #pragma unroll
            for (int j = 0; j < 16; j++) {
                uint2 bb = *(const uint2*)&Vt[(8*j + r4)*VPH + 16*t + 4*c4];
                mma16(o[j][0], o[j][1], o[j][2], o[j][3],
                      aLo.x, aHi.x, aLo.y, aHi.y, bb.x, bb.y);
            }
        }
    }

    rs_lo += __shfl_xor_sync(0xffffffffu, rs_lo, 1);
    rs_lo += __shfl_xor_sync(0xffffffffu, rs_lo, 2);
    rs_hi += __shfl_xor_sync(0xffffffffu, rs_hi, 1);
    rs_hi += __shfl_xor_sync(0xffffffffu, rs_hi, 2);
    float inv_lo = 1.f / rs_lo;
    float inv_hi = 1.f / rs_hi;
    #pragma unroll
    for (int j = 0; j < 16; j++) {
        int d = 8*j + 2*c4;
        size_t blo = ((size_t)bh * NS + mlo) * ND + d;
        size_t bhi = ((size_t)bh * NS + mhi) * ND + d;
        *(float2*)&g_ctx[blo] = make_float2(o[j][0] * inv_lo, o[j][1] * inv_lo);
        *(float2*)&g_ctx[bhi] = make_float2(o[j][2] * inv_hi, o[j][3] * inv_hi);
    }
}

// ---------------------------------------------------------------------------
extern "C" void kernel_launch(void* const* d_in, const int* in_sizes, int n_in,
                              void* d_out, int out_size) {
    const float* x     = (const float*)d_in[0];
    const int*   edge  = (const int*)d_in[1];
    const float* W_in  = (const float*)d_in[2];
    const float* b_in  = (const float*)d_in[3];
    const float* W_out = (const float*)d_in[4];
    const float* b_out = (const float*)d_in[5];
    float* out = (float*)d_out;

    static const size_t attn_smem = ATTN_SMEM_HALVES * sizeof(__half); // 176128
    static const size_t proj_smem = PROJ_SMEM_FLOATS * sizeof(float);
    cudaFuncSetAttribute((const void*)attn_kernel,
                         cudaFuncAttributeMaxDynamicSharedMemorySize, (int)attn_smem);
    cudaFuncSetAttribute((const void*)qkv_kernel,
                         cudaFuncAttributeMaxDynamicSharedMemorySize, (int)proj_smem);
    cudaFuncSetAttribute((const void*)outproj_kernel,
                         cudaFuncAttributeMaxDynamicSharedMemorySize, (int)proj_smem);

    ln_stats_kernel<<<NB, 256>>>(x, edge);
    prep_kernel<<<78, 256>>>(edge, W_in, W_out);
    qkv_kernel<<<dim3(2, 128), 256, proj_smem>>>(x, b_in);
    vtrans_kernel<<<dim3(NB*NH, NS/32, ND/32), 256>>>();
    attn_kernel<<<NB * NH * (NS / 128), 256, attn_smem>>>();
    outproj_kernel<<<dim3(4, 128), 256, proj_smem>>>(b_out, out);
}

// round 9
// speedup vs baseline: 2.3018x; 1.2375x over previous
#include <cuda_runtime.h>
#include <cuda_fp16.h>
#include <math.h>
#include <stdint.h>

#define NB 16
#define NS 1024
#define ND 128
#define NH 4
#define LNEPS 1e-5f
#define SCALE 0.08838834764831845f

// Scratch (device globals: allocation-free per harness rules)
__device__ __half g_qh[NB*NH*NS*ND];       // [bh][s][d], scale folded, fp16
__device__ __half g_kh[NB*NH*NS*ND];       // [bh][s][d_slot16], fp16
__device__ float  g_v[NB*NH*NS*ND];        // [bh][s][d], f32 (vtrans input)
__device__ __half g_vth[NB*NH*NS*ND];      // [bh][d][s_slot16], fp16
__device__ float  g_ctx[NB*NH*NS*ND];
__device__ __half g_win_h[NH*3*ND*ND];     // W_in rows, fp16, slot16 k
__device__ __half g_wout_h[NH*ND*ND];      // W_out rows, fp16, slot16 k
__device__ float  g_mean[NB];
__device__ float  g_rstd[NB];
__device__ float  g_wsum[NH*3*ND];
__device__ unsigned long long g_mbits[NH*NS*16];
__device__ int    g_edge64;

// slot16: within each 16-group, order 0,1,8,9,2,3,10,11,4,5,12,13,6,7,14,15
__device__ __forceinline__ int slot16(int k) {
    return (k < 8) ? ((k >> 1) * 4 + (k & 1)) : (((k - 8) >> 1) * 4 + 2 + (k & 1));
}

__device__ __forceinline__ void mma16(float& d0, float& d1, float& d2, float& d3,
                                      uint32_t a0, uint32_t a1, uint32_t a2, uint32_t a3,
                                      uint32_t b0, uint32_t b1) {
    asm volatile("mma.sync.aligned.m16n8k16.row.col.f32.f16.f16.f32 "
                 "{%0,%1,%2,%3}, {%4,%5,%6,%7}, {%8,%9}, {%0,%1,%2,%3};"
                 : "+f"(d0), "+f"(d1), "+f"(d2), "+f"(d3)
                 : "r"(a0), "r"(a1), "r"(a2), "r"(a3), "r"(b0), "r"(b1));
}

__device__ __forceinline__ void cp16(void* dst_smem, const void* src_gmem) {
    uint32_t d = (uint32_t)__cvta_generic_to_shared(dst_smem);
    asm volatile("cp.async.cg.shared.global [%0], [%1], 16;" :: "r"(d), "l"(src_gmem));
}

__device__ __forceinline__ uint32_t h2u(__half2 h) {
    return *reinterpret_cast<uint32_t*>(&h);
}

// ---------------------------------------------------------------------------
// K1: LayerNorm stats + edge dtype sniff
// ---------------------------------------------------------------------------
__global__ void ln_stats_kernel(const float* __restrict__ x,
                                const int* __restrict__ edge) {
    int b = blockIdx.x;
    const float4* xb = (const float4*)(x + (size_t)b * NS * ND);
    const int n4 = NS * ND / 4;
    float s = 0.f, ss = 0.f;
    for (int i = threadIdx.x; i < n4; i += blockDim.x) {
        float4 v = xb[i];
        s  += v.x + v.y + v.z + v.w;
        ss += v.x*v.x + v.y*v.y + v.z*v.z + v.w*v.w;
    }
    __shared__ float sh[256], sh2[256];
    sh[threadIdx.x] = s; sh2[threadIdx.x] = ss;
    __syncthreads();
    for (int o = 128; o > 0; o >>= 1) {
        if (threadIdx.x < o) {
            sh[threadIdx.x]  += sh[threadIdx.x + o];
            sh2[threadIdx.x] += sh2[threadIdx.x + o];
        }
        __syncthreads();
    }
    if (threadIdx.x == 0) {
        float inv_n = 1.f / (float)(NS * ND);
        float mu  = sh[0] * inv_n;
        float var = sh2[0] * inv_n - mu * mu;
        g_mean[b] = mu;
        g_rstd[b] = rsqrtf(var + LNEPS);
        if (b == 0) {
            int any = 0;
            #pragma unroll
            for (int i = 0; i < 64; i++) any |= edge[2*i + 1];
            g_edge64 = (any == 0) ? 1 : 0;
        }
    }
}

// ---------------------------------------------------------------------------
// K1b: prep — edge bitmasks, W column sums, fp16 slot16 weight copies
// ---------------------------------------------------------------------------
__global__ void prep_kernel(const int* __restrict__ edge,
                            const float* __restrict__ W_in,
                            const float* __restrict__ W_out) {
    int blk = blockIdx.x;
    if (blk < 64) {
        int idx = blk * 256 + threadIdx.x;
        int s = idx >> 4, t64 = idx & 15;
        unsigned long long m0 = 0, m1 = 0, m2 = 0, m3 = 0;
        if (g_edge64) {
            const int4* p = (const int4*)(edge + 2*((size_t)s*NS + t64*64));
            #pragma unroll
            for (int i = 0; i < 32; i++) {
                int4 v = p[i];
                unsigned long long b0 = 1ull << (2*i), b1 = 1ull << (2*i+1);
                if (v.x == 1) m0 |= b0;  if (v.z == 1) m0 |= b1;
                if (v.x == 2) m1 |= b0;  if (v.z == 2) m1 |= b1;
                if (v.x == 3) m2 |= b0;  if (v.z == 3) m2 |= b1;
                if (v.x == 4) m3 |= b0;  if (v.z == 4) m3 |= b1;
            }
        } else {
            const int4* p = (const int4*)(edge + ((size_t)s*NS + t64*64));
            #pragma unroll
            for (int i = 0; i < 16; i++) {
                int4 v = p[i];
                int e[4] = {v.x, v.y, v.z, v.w};
                #pragma unroll
                for (int q = 0; q < 4; q++) {
                    unsigned long long b = 1ull << (4*i + q);
                    if (e[q] == 1) m0 |= b;
                    if (e[q] == 2) m1 |= b;
                    if (e[q] == 3) m2 |= b;
                    if (e[q] == 4) m3 |= b;
                }
            }
        }
        g_mbits[(0*NS + s)*16 + t64] = m0;
        g_mbits[(1*NS + s)*16 + t64] = m1;
        g_mbits[(2*NS + s)*16 + t64] = m2;
        g_mbits[(3*NS + s)*16 + t64] = m3;
    } else if (blk < 70) {
        int col = (blk - 64) * 256 + threadIdx.x;
        float s = 0.f;
        const float4* p = (const float4*)(W_in + (size_t)col * ND);
        #pragma unroll
        for (int i = 0; i < 32; i++) {
            float4 v = p[i];
            s += v.x + v.y + v.z + v.w;
        }
        g_wsum[col] = s;
    } else {
        // fp16 slot16-interleaved weight rows
        int row = (blk - 70) * 256 + threadIdx.x;   // 0..2047
        const float* src;
        __half* dst;
        if (row < 1536) { src = W_in  + (size_t)row * ND;          dst = g_win_h  + (size_t)row * ND; }
        else            { src = W_out + (size_t)(row - 1536) * ND; dst = g_wout_h + (size_t)(row - 1536) * ND; }
        #pragma unroll
        for (int g = 0; g < 8; g++) {
            float4 A0 = *(const float4*)&src[16*g];
            float4 A1 = *(const float4*)&src[16*g + 4];
            float4 A2 = *(const float4*)&src[16*g + 8];
            float4 A3 = *(const float4*)&src[16*g + 12];
            __half2 h[8];
            h[0] = __floats2half2_rn(A0.x, A0.y);   // slots 0,1   = k 0,1
            h[1] = __floats2half2_rn(A2.x, A2.y);   // slots 2,3   = k 8,9
            h[2] = __floats2half2_rn(A0.z, A0.w);   // slots 4,5   = k 2,3
            h[3] = __floats2half2_rn(A2.z, A2.w);   // slots 6,7   = k 10,11
            h[4] = __floats2half2_rn(A1.x, A1.y);   // slots 8,9   = k 4,5
            h[5] = __floats2half2_rn(A3.x, A3.y);   // slots 10,11 = k 12,13
            h[6] = __floats2half2_rn(A1.z, A1.w);   // slots 12,13 = k 6,7
            h[7] = __floats2half2_rn(A3.z, A3.w);   // slots 14,15 = k 14,15
            *(uint4*)&dst[16*g]     = *(const uint4*)&h[0];
            *(uint4*)&dst[16*g + 8] = *(const uint4*)&h[4];
        }
    }
}

// ---------------------------------------------------------------------------
// K2b: V transpose f32 -> f16, d-major, slot16-interleaved s
// ---------------------------------------------------------------------------
__global__ void vtrans_kernel() {
    __shared__ float tile[32][33];
    const int bh = blockIdx.x;
    const int s0 = blockIdx.y * 32;
    const int d0 = blockIdx.z * 32;
    const int tx = threadIdx.x & 31;
    const int ty = threadIdx.x >> 5;
    const float* src = g_v + (size_t)bh * NS * ND;
    __half* dst = g_vth + (size_t)bh * ND * NS;
    #pragma unroll
    for (int i = 0; i < 4; i++) {
        int sy = ty + 8*i;
        tile[sy][tx] = src[(size_t)(s0 + sy) * ND + d0 + tx];
    }
    __syncthreads();
    const int sp = s0 + (tx & 16) + slot16(tx & 15);
    #pragma unroll
    for (int i = 0; i < 4; i++) {
        int d = d0 + ty + 8*i;
        dst[(size_t)d * NS + sp] = __float2half_rn(tile[tx][ty + 8*i]);
    }
}

// ---------------------------------------------------------------------------
// Projection kernels: fp16 mma.m16n8k16; A f32-staged (converted at gather),
// B fp16 slot16 -> one conflict-free LDS.64 per B-fragment. 2 CTAs/SM.
// ---------------------------------------------------------------------------
#define APJ 132                 // A staging pad (f32)
#define BPH 144                 // B tile row stride (halves): 288B -> CF LDS.64
#define PROJ_SMEM_BYTES (128*APJ*4 + 2*64*BPH*2)   // 67584 + 36864 = 104448

// K2: fused LN + QKV projection; writes q/k as fp16 (q scaled, k slot16), v f32
__global__ __launch_bounds__(256, 2) void qkv_kernel(const float* __restrict__ x,
                                                     const float* __restrict__ b_in) {
    extern __shared__ char sgc[];
    float* As = (float*)sgc;
    __half* Bs0 = (__half*)(sgc + 128*APJ*4);
    __half* Bs1 = Bs0 + 64*BPH;

    const int tid  = threadIdx.x;
    const int w    = tid >> 5;
    const int lane = tid & 31;
    const int r4   = lane >> 2;
    const int c4   = lane & 3;

    const int colbase = blockIdx.x * 768;
    const int m0 = blockIdx.y * 128;
    const int b  = blockIdx.y >> 3;
    const float mean = g_mean[b], rstd = g_rstd[b];
    const float mr = mean * rstd;

    // A (raw x, f32) + B tile 0 (fp16)
    #pragma unroll
    for (int i = 0; i < 16; i++) {
        int q = i * 256 + tid;
        int row = q >> 5, c = (q & 31) * 4;
        cp16(&As[row*APJ + c], &x[(size_t)(m0 + row) * ND + c]);
    }
    #pragma unroll
    for (int i = 0; i < 4; i++) {
        int q = i * 256 + tid;
        int row = q >> 4, c = (q & 15) * 8;
        cp16(&Bs0[row*BPH + c], &g_win_h[(size_t)(colbase + row) * ND + c]);
    }
    asm volatile("cp.async.commit_group;");
    asm volatile("cp.async.wait_group 0;");
    __syncthreads();

    // Gather A fragments as fp16 (one-time conversion)
    uint32_t Ah[32];
    {
        const int rl = 16*w + r4;
        #pragma unroll
        for (int t = 0; t < 8; t++) {
            float2 lo0 = *(const float2*)&As[(rl    )*APJ + 16*t + 2*c4    ];
            float2 lo1 = *(const float2*)&As[(rl + 8)*APJ + 16*t + 2*c4    ];
            float2 hi0 = *(const float2*)&As[(rl    )*APJ + 16*t + 2*c4 + 8];
            float2 hi1 = *(const float2*)&As[(rl + 8)*APJ + 16*t + 2*c4 + 8];
            Ah[4*t+0] = h2u(__floats2half2_rn(lo0.x, lo0.y));
            Ah[4*t+1] = h2u(__floats2half2_rn(lo1.x, lo1.y));
            Ah[4*t+2] = h2u(__floats2half2_rn(hi0.x, hi0.y));
            Ah[4*t+3] = h2u(__floats2half2_rn(hi1.x, hi1.y));
        }
    }

    const int rlo = m0 + 16*w + r4;
    const int rhi = rlo + 8;
    const int slo = rlo & (NS - 1);
    const int shi = rhi & (NS - 1);

    #define NTQ 12
    for (int nt = 0; nt < NTQ; nt++) {
        const int buf = nt & 1;
        __half* Bcur = buf ? Bs1 : Bs0;
        __half* Bnxt = buf ? Bs0 : Bs1;
        if (nt + 1 < NTQ) {
            const int nrow = colbase + (nt + 1) * 64;
            #pragma unroll
            for (int i = 0; i < 4; i++) {
                int q = i * 256 + tid;
                int row = q >> 4, c = (q & 15) * 8;
                cp16(&Bnxt[row*BPH + c], &g_win_h[(size_t)(nrow + row) * ND + c]);
            }
            asm volatile("cp.async.commit_group;");
        }

        float acc[8][4];
        #pragma unroll
        for (int j = 0; j < 8; j++)
            #pragma unroll
            for (int k = 0; k < 4; k++) acc[j][k] = 0.f;

        #pragma unroll
        for (int t = 0; t < 8; t++) {
            uint32_t a0 = Ah[4*t], a1 = Ah[4*t+1], a2 = Ah[4*t+2], a3 = Ah[4*t+3];
            #pragma unroll
            for (int j = 0; j < 8; j++) {
                uint2 bb = *(const uint2*)&Bcur[(8*j + r4)*BPH + 16*t + 4*c4];
                mma16(acc[j][0], acc[j][1], acc[j][2], acc[j][3],
                      a0, a1, a2, a3, bb.x, bb.y);
            }
        }

        const int n0 = colbase + nt * 64;
        #pragma unroll
        for (int j = 0; j < 8; j++) {
            int colg = n0 + 8*j + 2*c4;
            float2 bias = *(const float2*)&b_in[colg];
            float2 ws   = *(const float2*)&g_wsum[colg];
            float off0 = bias.x - mr * ws.x;
            float off1 = bias.y - mr * ws.y;
            float v00 = rstd*acc[j][0] + off0, v01 = rstd*acc[j][1] + off1;
            float v10 = rstd*acc[j][2] + off0, v11 = rstd*acc[j][3] + off1;
            int hh = colg / 384;
            int r  = colg - hh * 384;
            int which = r >> 7;
            int d = r & 127;
            size_t base = ((size_t)(b*NH + hh)) * NS * ND;
            if (which == 0) {
                *(__half2*)&g_qh[base + (size_t)slo * ND + d] =
                    __floats2half2_rn(v00 * SCALE, v01 * SCALE);
                *(__half2*)&g_qh[base + (size_t)shi * ND + d] =
                    __floats2half2_rn(v10 * SCALE, v11 * SCALE);
            } else if (which == 1) {
                int dl = d & 15;
                int sb = (dl < 8) ? (dl * 2) : ((dl - 8) * 2 + 2);
                int dp = (d & ~15) | sb;
                *(__half2*)&g_kh[base + (size_t)slo * ND + dp] = __floats2half2_rn(v00, v01);
                *(__half2*)&g_kh[base + (size_t)shi * ND + dp] = __floats2half2_rn(v10, v11);
            } else {
                *(float2*)&g_v[base + (size_t)slo * ND + d] = make_float2(v00, v01);
                *(float2*)&g_v[base + (size_t)shi * ND + d] = make_float2(v10, v11);
            }
        }

        if (nt + 1 < NTQ) {
            asm volatile("cp.async.wait_group 0;");
            __syncthreads();
        }
    }
}

// K4: out projection (fp16 mma)
__global__ __launch_bounds__(256, 2) void outproj_kernel(const float* __restrict__ b_out,
                                                         float* __restrict__ out) {
    extern __shared__ char sgc[];
    float* As = (float*)sgc;
    __half* Bs0 = (__half*)(sgc + 128*APJ*4);
    __half* Bs1 = Bs0 + 64*BPH;

    const int tid  = threadIdx.x;
    const int w    = tid >> 5;
    const int lane = tid & 31;
    const int r4   = lane >> 2;
    const int c4   = lane & 3;

    const int hh = blockIdx.x;
    const int m0 = blockIdx.y * 128;
    const int b  = blockIdx.y >> 3;
    const int s0 = m0 & (NS - 1);
    const float* Ag = g_ctx + ((size_t)(b*NH + hh) * NS + s0) * ND;
    const int colbase = hh * 128;

    #pragma unroll
    for (int i = 0; i < 16; i++) {
        int q = i * 256 + tid;
        int row = q >> 5, c = (q & 31) * 4;
        cp16(&As[row*APJ + c], &Ag[(size_t)row * ND + c]);
    }
    #pragma unroll
    for (int i = 0; i < 4; i++) {
        int q = i * 256 + tid;
        int row = q >> 4, c = (q & 15) * 8;
        cp16(&Bs0[row*BPH + c], &g_wout_h[(size_t)(colbase + row) * ND + c]);
    }
    asm volatile("cp.async.commit_group;");
    asm volatile("cp.async.wait_group 0;");
    __syncthreads();

    uint32_t Ah[32];
    {
        const int rl = 16*w + r4;
        #pragma unroll
        for (int t = 0; t < 8; t++) {
            float2 lo0 = *(const float2*)&As[(rl    )*APJ + 16*t + 2*c4    ];
            float2 lo1 = *(const float2*)&As[(rl + 8)*APJ + 16*t + 2*c4    ];
            float2 hi0 = *(const float2*)&As[(rl    )*APJ + 16*t + 2*c4 + 8];
            float2 hi1 = *(const float2*)&As[(rl + 8)*APJ + 16*t + 2*c4 + 8];
            Ah[4*t+0] = h2u(__floats2half2_rn(lo0.x, lo0.y));
            Ah[4*t+1] = h2u(__floats2half2_rn(lo1.x, lo1.y));
            Ah[4*t+2] = h2u(__floats2half2_rn(hi0.x, hi0.y));
            Ah[4*t+3] = h2u(__floats2half2_rn(hi1.x, hi1.y));
        }
    }

    const int rlo = m0 + 16*w + r4;
    const int rhi = rlo + 8;

    #pragma unroll
    for (int nt = 0; nt < 2; nt++) {
        __half* Bcur = nt ? Bs1 : Bs0;
        __half* Bnxt = nt ? Bs0 : Bs1;
        if (nt == 0) {
            const int nrow = colbase + 64;
            #pragma unroll
            for (int i = 0; i < 4; i++) {
                int q = i * 256 + tid;
                int row = q >> 4, c = (q & 15) * 8;
                cp16(&Bnxt[row*BPH + c], &g_wout_h[(size_t)(nrow + row) * ND + c]);
            }
            asm volatile("cp.async.commit_group;");
        }

        float acc[8][4];
        #pragma unroll
        for (int j = 0; j < 8; j++)
            #pragma unroll
            for (int k = 0; k < 4; k++) acc[j][k] = 0.f;

        #pragma unroll
        for (int t = 0; t < 8; t++) {
            uint32_t a0 = Ah[4*t], a1 = Ah[4*t+1], a2 = Ah[4*t+2], a3 = Ah[4*t+3];
            #pragma unroll
            for (int j = 0; j < 8; j++) {
                uint2 bb = *(const uint2*)&Bcur[(8*j + r4)*BPH + 16*t + 4*c4];
                mma16(acc[j][0], acc[j][1], acc[j][2], acc[j][3],
                      a0, a1, a2, a3, bb.x, bb.y);
            }
        }

        const int n0 = colbase + nt * 64;
        #pragma unroll
        for (int j = 0; j < 8; j++) {
            int colg = n0 + 8*j + 2*c4;
            float2 bias = *(const float2*)&b_out[colg];
            *(float2*)&out[(size_t)rlo * (NH*ND) + colg] =
                make_float2(acc[j][0] + bias.x, acc[j][1] + bias.y);
            *(float2*)&out[(size_t)rhi * (NH*ND) + colg] =
                make_float2(acc[j][2] + bias.x, acc[j][3] + bias.y);
        }

        if (nt == 0) {
            asm volatile("cp.async.wait_group 0;");
            __syncthreads();
        }
    }
}

// ---------------------------------------------------------------------------
// K3: flash attention (unchanged from R8 — protect the win)
// ---------------------------------------------------------------------------
#define KPH 144
#define VPH 80
#define PPH 80
#define QSH 136
#define OFF_K   0
#define OFF_V   (4*64*KPH)
#define OFF_P   (OFF_V + 4*128*VPH)
#define OFF_QSTG (OFF_V + 128*VPH)
#define ATTN_SMEM_HALVES (OFF_P + 128*PPH)

__device__ __forceinline__ void load_kv_async(const __half* __restrict__ Kg,
                                              const __half* __restrict__ Vg,
                                              int n0, __half* Ks, __half* Vt, int tid) {
    #pragma unroll
    for (int i = 0; i < 4; i++) {
        int q = i * 256 + tid;
        int kr = q >> 4, kc = (q & 15) * 8;
        cp16(&Ks[kr*KPH + kc], Kg + (size_t)(n0 + kr) * ND + kc);
        int vr = q >> 3, vc = (q & 7) * 8;
        cp16(&Vt[vr*VPH + vc], Vg + (size_t)vr * NS + n0 + vc);
    }
}

__global__ __launch_bounds__(256, 1) void attn_kernel() {
    extern __shared__ __half smh[];
    const int tid  = threadIdx.x;
    const int w    = tid >> 5;
    const int lane = tid & 31;
    const int r4   = lane >> 2;
    const int c4   = lane & 3;

    const int bh = blockIdx.x >> 3;
    const int qt = blockIdx.x & 7;
    const int h  = bh & 3;
    const int m0 = qt * 128;

    const __half* Qg = g_qh  + (size_t)bh * NS * ND;
    const __half* Kg = g_kh  + (size_t)bh * NS * ND;
    const __half* Vg = g_vth + (size_t)bh * ND * NS;

    load_kv_async(Kg, Vg, 0, smh + OFF_K, smh + OFF_V, tid);
    asm volatile("cp.async.commit_group;");

    {
        __half* Qstg = smh + OFF_QSTG;
        #pragma unroll
        for (int i = 0; i < 8; i++) {
            int q = i * 256 + tid;
            int row = q >> 4, ch = (q & 15) * 8;
            *(uint4*)&Qstg[row*QSH + ch] =
                *(const uint4*)&Qg[(size_t)(m0 + row) * ND + ch];
        }
    }
    __syncthreads();

    uint32_t Qf[32];
    {
        const __half* Qstg = smh + OFF_QSTG;
        const int rl = 16*w + r4;
        #pragma unroll
        for (int t = 0; t < 8; t++) {
            Qf[4*t+0] = *(const uint32_t*)&Qstg[(rl    )*QSH + 16*t + 2*c4    ];
            Qf[4*t+1] = *(const uint32_t*)&Qstg[(rl + 8)*QSH + 16*t + 2*c4    ];
            Qf[4*t+2] = *(const uint32_t*)&Qstg[(rl    )*QSH + 16*t + 2*c4 + 8];
            Qf[4*t+3] = *(const uint32_t*)&Qstg[(rl + 8)*QSH + 16*t + 2*c4 + 8];
        }
    }
    __syncthreads();

    load_kv_async(Kg, Vg, 64,  smh + OFF_K + 1*64*KPH, smh + OFF_V + 1*128*VPH, tid);
    asm volatile("cp.async.commit_group;");
    load_kv_async(Kg, Vg, 128, smh + OFF_K + 2*64*KPH, smh + OFF_V + 2*128*VPH, tid);
    asm volatile("cp.async.commit_group;");

    float o[16][4];
    #pragma unroll
    for (int j = 0; j < 16; j++)
        #pragma unroll
        for (int k = 0; k < 4; k++) o[j][k] = 0.f;
    float rs_lo = 0.f, rs_hi = 0.f;

    __half* Psw = smh + OFF_P + (w * 16) * PPH;
    const int mlo = m0 + 16*w + r4;
    const int mhi = mlo + 8;
    const unsigned long long* mb_lo_base = &g_mbits[((size_t)h*NS + mlo)*16];
    const unsigned long long* mb_hi_base = &g_mbits[((size_t)h*NS + mhi)*16];

    for (int it = 0; it < 16; ++it) {
        if (it < 14)       { asm volatile("cp.async.wait_group 2;"); }
        else if (it == 14) { asm volatile("cp.async.wait_group 1;"); }
        else               { asm volatile("cp.async.wait_group 0;"); }
        __syncthreads();
        if (it + 3 < 16) {
            int nslot = (it + 3) & 3;
            load_kv_async(Kg, Vg, (it + 3) * 64,
                          smh + OFF_K + nslot*64*KPH,
                          smh + OFF_V + nslot*128*VPH, tid);
            asm volatile("cp.async.commit_group;");
        }

        const __half* Ks = smh + OFF_K + (it & 3) * 64 * KPH;
        const __half* Vt = smh + OFF_V + (it & 3) * 128 * VPH;
        const unsigned long long mb_lo = mb_lo_base[it];
        const unsigned long long mb_hi = mb_hi_base[it];

        float acc[8][4];
        #pragma unroll
        for (int j = 0; j < 8; j++)
            #pragma unroll
            for (int k = 0; k < 4; k++) acc[j][k] = 0.f;

        #pragma unroll
        for (int t = 0; t < 8; t++) {
            uint32_t a0 = Qf[4*t], a1 = Qf[4*t+1], a2 = Qf[4*t+2], a3 = Qf[4*t+3];
            #pragma unroll
            for (int j = 0; j < 8; j++) {
                uint2 bb = *(const uint2*)&Ks[(8*j + r4)*KPH + 16*t + 4*c4];
                mma16(acc[j][0], acc[j][1], acc[j][2], acc[j][3],
                      a0, a1, a2, a3, bb.x, bb.y);
            }
        }

        #pragma unroll
        for (int j = 0; j < 8; j++) {
            unsigned blo = (unsigned)(mb_lo >> (8*j + 2*c4));
            unsigned bhi = (unsigned)(mb_hi >> (8*j + 2*c4));
            float p0 = (blo & 1u) ? __expf(acc[j][0]) : 0.f;
            float p1 = (blo & 2u) ? __expf(acc[j][1]) : 0.f;
            float p2 = (bhi & 1u) ? __expf(acc[j][2]) : 0.f;
            float p3 = (bhi & 2u) ? __expf(acc[j][3]) : 0.f;
            __half2 hlo = __floats2half2_rn(p0, p1);
            __half2 hhi = __floats2half2_rn(p2, p3);
            float2 flo = __half22float2(hlo);
            float2 fhi = __half22float2(hhi);
            rs_lo += flo.x + flo.y;
            rs_hi += fhi.x + fhi.y;
            int off = (j >> 1) * 16 + 4*c4 + 2*(j & 1);
            *(__half2*)&Psw[(r4    )*PPH + off] = hlo;
            *(__half2*)&Psw[(r4 + 8)*PPH + off] = hhi;
        }
        __syncwarp();

        #pragma unroll
        for (int t = 0; t < 4; t++) {
            uint2 aLo = *(const uint2*)&Psw[(r4    )*PPH + 16*t + 4*c4];
            uint2 aHi = *(const uint2*)&Psw[(r4 + 8)*PPH + 16*t + 4*c4];
            #pragma unroll
            for (int j = 0; j < 16; j++) {
                uint2 bb = *(const uint2*)&Vt[(8*j + r4)*VPH + 16*t + 4*c4];
                mma16(o[j][0], o[j][1], o[j][2], o[j][3],
                      aLo.x, aHi.x, aLo.y, aHi.y, bb.x, bb.y);
            }
        }
    }

    rs_lo += __shfl_xor_sync(0xffffffffu, rs_lo, 1);
    rs_lo += __shfl_xor_sync(0xffffffffu, rs_lo, 2);
    rs_hi += __shfl_xor_sync(0xffffffffu, rs_hi, 1);
    rs_hi += __shfl_xor_sync(0xffffffffu, rs_hi, 2);
    float inv_lo = 1.f / rs_lo;
    float inv_hi = 1.f / rs_hi;
    #pragma unroll
    for (int j = 0; j < 16; j++) {
        int d = 8*j + 2*c4;
        size_t blo = ((size_t)bh * NS + mlo) * ND + d;
        size_t bhi = ((size_t)bh * NS + mhi) * ND + d;
        *(float2*)&g_ctx[blo] = make_float2(o[j][0] * inv_lo, o[j][1] * inv_lo);
        *(float2*)&g_ctx[bhi] = make_float2(o[j][2] * inv_hi, o[j][3] * inv_hi);
    }
}

// ---------------------------------------------------------------------------
extern "C" void kernel_launch(void* const* d_in, const int* in_sizes, int n_in,
                              void* d_out, int out_size) {
    const float* x     = (const float*)d_in[0];
    const int*   edge  = (const int*)d_in[1];
    const float* W_in  = (const float*)d_in[2];
    const float* b_in  = (const float*)d_in[3];
    const float* W_out = (const float*)d_in[4];
    const float* b_out = (const float*)d_in[5];
    float* out = (float*)d_out;

    static const size_t attn_smem = ATTN_SMEM_HALVES * sizeof(__half); // 176128
    static const size_t proj_smem = PROJ_SMEM_BYTES;                   // 104448
    cudaFuncSetAttribute((const void*)attn_kernel,
                         cudaFuncAttributeMaxDynamicSharedMemorySize, (int)attn_smem);
    cudaFuncSetAttribute((const void*)qkv_kernel,
                         cudaFuncAttributeMaxDynamicSharedMemorySize, (int)proj_smem);
    cudaFuncSetAttribute((const void*)outproj_kernel,
                         cudaFuncAttributeMaxDynamicSharedMemorySize, (int)proj_smem);

    ln_stats_kernel<<<NB, 256>>>(x, edge);
    prep_kernel<<<78, 256>>>(edge, W_in, W_out);
    qkv_kernel<<<dim3(2, 128), 256, proj_smem>>>(x, b_in);
    vtrans_kernel<<<dim3(NB*NH, NS/32, ND/32), 256>>>();
    attn_kernel<<<NB * NH * (NS / 128), 256, attn_smem>>>();
    outproj_kernel<<<dim3(4, 128), 256, proj_smem>>>(b_out, out);
}

// round 10
// speedup vs baseline: 2.5262x; 1.0975x over previous
#include <cuda_runtime.h>
#include <cuda_fp16.h>
#include <math.h>
#include <stdint.h>

#define NB 16
#define NS 1024
#define ND 128
#define NH 4
#define LNEPS 1e-5f
#define SCALE 0.08838834764831845f

// Scratch (device globals: allocation-free per harness rules)
__device__ __half g_qh[NB*NH*NS*ND];       // [bh][s][d], scale folded, fp16
__device__ __half g_kh[NB*NH*NS*ND];       // [bh][s][d_slot16], fp16
__device__ __half g_vth[NB*NH*NS*ND];      // [bh][d][s_slot16], fp16
__device__ float  g_ctx[NB*NH*NS*ND];
__device__ __half g_win_h[NH*3*ND*ND];     // W_in rows, fp16, slot16 k
__device__ __half g_wout_h[NH*ND*ND];      // W_out rows, fp16, slot16 k
__device__ float  g_psum[NB*8];
__device__ float  g_psum2[NB*8];
__device__ float  g_mean[NB];
__device__ float  g_rstd[NB];
__device__ float  g_wsum[NH*3*ND];
__device__ unsigned long long g_mbits[NH*NS*16];
__device__ int    g_edge64;

// slot16: within each 16-group, order 0,1,8,9,2,3,10,11,4,5,12,13,6,7,14,15
__device__ __forceinline__ int slot16(int k) {
    return (k < 8) ? ((k >> 1) * 4 + (k & 1)) : (((k - 8) >> 1) * 4 + 2 + (k & 1));
}

__device__ __forceinline__ void mma16(float& d0, float& d1, float& d2, float& d3,
                                      uint32_t a0, uint32_t a1, uint32_t a2, uint32_t a3,
                                      uint32_t b0, uint32_t b1) {
    asm volatile("mma.sync.aligned.m16n8k16.row.col.f32.f16.f16.f32 "
                 "{%0,%1,%2,%3}, {%4,%5,%6,%7}, {%8,%9}, {%0,%1,%2,%3};"
                 : "+f"(d0), "+f"(d1), "+f"(d2), "+f"(d3)
                 : "r"(a0), "r"(a1), "r"(a2), "r"(a3), "r"(b0), "r"(b1));
}

__device__ __forceinline__ void cp16(void* dst_smem, const void* src_gmem) {
    uint32_t d = (uint32_t)__cvta_generic_to_shared(dst_smem);
    asm volatile("cp.async.cg.shared.global [%0], [%1], 16;" :: "r"(d), "l"(src_gmem));
}

__device__ __forceinline__ uint32_t h2u(__half2 h) {
    return *reinterpret_cast<uint32_t*>(&h);
}

// ---------------------------------------------------------------------------
// K1a: LN partial sums (128 blocks: 8 per batch)
// ---------------------------------------------------------------------------
__global__ void ln_partial_kernel(const float* __restrict__ x) {
    const int b = blockIdx.x >> 3;
    const int part = blockIdx.x & 7;
    const float4* xb = (const float4*)(x + (size_t)b * NS * ND) + part * 4096;
    float s = 0.f, ss = 0.f;
    #pragma unroll
    for (int i = 0; i < 16; i++) {
        float4 v = xb[i * 256 + threadIdx.x];
        s  += v.x + v.y + v.z + v.w;
        ss += v.x*v.x + v.y*v.y + v.z*v.z + v.w*v.w;
    }
    __shared__ float sh[256], sh2[256];
    sh[threadIdx.x] = s; sh2[threadIdx.x] = ss;
    __syncthreads();
    for (int o = 128; o > 0; o >>= 1) {
        if (threadIdx.x < o) {
            sh[threadIdx.x]  += sh[threadIdx.x + o];
            sh2[threadIdx.x] += sh2[threadIdx.x + o];
        }
        __syncthreads();
    }
    if (threadIdx.x == 0) {
        g_psum[blockIdx.x]  = sh[0];
        g_psum2[blockIdx.x] = sh2[0];
    }
}

// K1b: finalize mean/rstd + edge dtype sniff (1 block)
__global__ void ln_final_kernel(const int* __restrict__ edge) {
    int t = threadIdx.x;
    if (t < NB) {
        float s = 0.f, ss = 0.f;
        #pragma unroll
        for (int i = 0; i < 8; i++) { s += g_psum[t*8 + i]; ss += g_psum2[t*8 + i]; }
        float inv_n = 1.f / (float)(NS * ND);
        float mu  = s * inv_n;
        float var = ss * inv_n - mu * mu;
        g_mean[t] = mu;
        g_rstd[t] = rsqrtf(var + LNEPS);
    } else if (t == 32) {
        int any = 0;
        #pragma unroll
        for (int i = 0; i < 64; i++) any |= edge[2*i + 1];
        g_edge64 = (any == 0) ? 1 : 0;
    }
}

// ---------------------------------------------------------------------------
// K1c: prep — edge bitmasks, W column sums, fp16 slot16 weight copies
// ---------------------------------------------------------------------------
__global__ void prep_kernel(const int* __restrict__ edge,
                            const float* __restrict__ W_in,
                            const float* __restrict__ W_out) {
    int blk = blockIdx.x;
    if (blk < 64) {
        int idx = blk * 256 + threadIdx.x;
        int s = idx >> 4, t64 = idx & 15;
        unsigned long long m0 = 0, m1 = 0, m2 = 0, m3 = 0;
        if (g_edge64) {
            const int4* p = (const int4*)(edge + 2*((size_t)s*NS + t64*64));
            #pragma unroll
            for (int i = 0; i < 32; i++) {
                int4 v = p[i];
                unsigned long long b0 = 1ull << (2*i), b1 = 1ull << (2*i+1);
                if (v.x == 1) m0 |= b0;  if (v.z == 1) m0 |= b1;
                if (v.x == 2) m1 |= b0;  if (v.z == 2) m1 |= b1;
                if (v.x == 3) m2 |= b0;  if (v.z == 3) m2 |= b1;
                if (v.x == 4) m3 |= b0;  if (v.z == 4) m3 |= b1;
            }
        } else {
            const int4* p = (const int4*)(edge + ((size_t)s*NS + t64*64));
            #pragma unroll
            for (int i = 0; i < 16; i++) {
                int4 v = p[i];
                int e[4] = {v.x, v.y, v.z, v.w};
                #pragma unroll
                for (int q = 0; q < 4; q++) {
                    unsigned long long b = 1ull << (4*i + q);
                    if (e[q] == 1) m0 |= b;
                    if (e[q] == 2) m1 |= b;
                    if (e[q] == 3) m2 |= b;
                    if (e[q] == 4) m3 |= b;
                }
            }
        }
        g_mbits[(0*NS + s)*16 + t64] = m0;
        g_mbits[(1*NS + s)*16 + t64] = m1;
        g_mbits[(2*NS + s)*16 + t64] = m2;
        g_mbits[(3*NS + s)*16 + t64] = m3;
    } else if (blk < 70) {
        int col = (blk - 64) * 256 + threadIdx.x;
        float s = 0.f;
        const float4* p = (const float4*)(W_in + (size_t)col * ND);
        #pragma unroll
        for (int i = 0; i < 32; i++) {
            float4 v = p[i];
            s += v.x + v.y + v.z + v.w;
        }
        g_wsum[col] = s;
    } else {
        // fp16 slot16-interleaved weight rows
        int row = (blk - 70) * 256 + threadIdx.x;   // 0..2047
        const float* src;
        __half* dst;
        if (row < 1536) { src = W_in  + (size_t)row * ND;          dst = g_win_h  + (size_t)row * ND; }
        else            { src = W_out + (size_t)(row - 1536) * ND; dst = g_wout_h + (size_t)(row - 1536) * ND; }
        #pragma unroll
        for (int g = 0; g < 8; g++) {
            float4 A0 = *(const float4*)&src[16*g];
            float4 A1 = *(const float4*)&src[16*g + 4];
            float4 A2 = *(const float4*)&src[16*g + 8];
            float4 A3 = *(const float4*)&src[16*g + 12];
            __half2 h[8];
            h[0] = __floats2half2_rn(A0.x, A0.y);
            h[1] = __floats2half2_rn(A2.x, A2.y);
            h[2] = __floats2half2_rn(A0.z, A0.w);
            h[3] = __floats2half2_rn(A2.z, A2.w);
            h[4] = __floats2half2_rn(A1.x, A1.y);
            h[5] = __floats2half2_rn(A3.x, A3.y);
            h[6] = __floats2half2_rn(A1.z, A1.w);
            h[7] = __floats2half2_rn(A3.z, A3.w);
            *(uint4*)&dst[16*g]     = *(const uint4*)&h[0];
            *(uint4*)&dst[16*g + 8] = *(const uint4*)&h[4];
        }
    }
}

// ---------------------------------------------------------------------------
// Projection kernels: fp16 mma.m16n8k16; A f32-staged (converted at gather),
// B fp16 slot16 -> one conflict-free LDS.64 per B-fragment. 2 CTAs/SM.
// ---------------------------------------------------------------------------
#define APJ 132
#define BPH 144
#define PROJ_SMEM_BYTES (128*APJ*4 + 2*64*BPH*2)   // 104448

// K2: fused LN + QKV projection; writes q/k fp16 + V DIRECTLY into g_vth
__global__ __launch_bounds__(256, 2) void qkv_kernel(const float* __restrict__ x,
                                                     const float* __restrict__ b_in) {
    extern __shared__ char sgc[];
    float* As = (float*)sgc;
    __half* Bs0 = (__half*)(sgc + 128*APJ*4);
    __half* Bs1 = Bs0 + 64*BPH;

    const int tid  = threadIdx.x;
    const int w    = tid >> 5;
    const int lane = tid & 31;
    const int r4   = lane >> 2;
    const int c4   = lane & 3;

    const int colbase = blockIdx.x * 768;
    const int m0 = blockIdx.y * 128;
    const int b  = blockIdx.y >> 3;
    const float mean = g_mean[b], rstd = g_rstd[b];
    const float mr = mean * rstd;

    #pragma unroll
    for (int i = 0; i < 16; i++) {
        int q = i * 256 + tid;
        int row = q >> 5, c = (q & 31) * 4;
        cp16(&As[row*APJ + c], &x[(size_t)(m0 + row) * ND + c]);
    }
    #pragma unroll
    for (int i = 0; i < 4; i++) {
        int q = i * 256 + tid;
        int row = q >> 4, c = (q & 15) * 8;
        cp16(&Bs0[row*BPH + c], &g_win_h[(size_t)(colbase + row) * ND + c]);
    }
    asm volatile("cp.async.commit_group;");
    asm volatile("cp.async.wait_group 0;");
    __syncthreads();

    uint32_t Ah[32];
    {
        const int rl = 16*w + r4;
        #pragma unroll
        for (int t = 0; t < 8; t++) {
            float2 lo0 = *(const float2*)&As[(rl    )*APJ + 16*t + 2*c4    ];
            float2 lo1 = *(const float2*)&As[(rl + 8)*APJ + 16*t + 2*c4    ];
            float2 hi0 = *(const float2*)&As[(rl    )*APJ + 16*t + 2*c4 + 8];
            float2 hi1 = *(const float2*)&As[(rl + 8)*APJ + 16*t + 2*c4 + 8];
            Ah[4*t+0] = h2u(__floats2half2_rn(lo0.x, lo0.y));
            Ah[4*t+1] = h2u(__floats2half2_rn(lo1.x, lo1.y));
            Ah[4*t+2] = h2u(__floats2half2_rn(hi0.x, hi0.y));
            Ah[4*t+3] = h2u(__floats2half2_rn(hi1.x, hi1.y));
        }
    }

    const int rlo = m0 + 16*w + r4;
    const int rhi = rlo + 8;
    const int slo = rlo & (NS - 1);
    const int shi = rhi & (NS - 1);
    const int splo = (slo & ~15) | slot16(slo & 15);
    const int sphi = (shi & ~15) | slot16(shi & 15);

    #define NTQ 12
    for (int nt = 0; nt < NTQ; nt++) {
        const int buf = nt & 1;
        __half* Bcur = buf ? Bs1 : Bs0;
        __half* Bnxt = buf ? Bs0 : Bs1;
        if (nt + 1 < NTQ) {
            const int nrow = colbase + (nt + 1) * 64;
            #pragma unroll
            for (int i = 0; i < 4; i++) {
                int q = i * 256 + tid;
                int row = q >> 4, c = (q & 15) * 8;
                cp16(&Bnxt[row*BPH + c], &g_win_h[(size_t)(nrow + row) * ND + c]);
            }
            asm volatile("cp.async.commit_group;");
        }

        float acc[8][4];
        #pragma unroll
        for (int j = 0; j < 8; j++)
            #pragma unroll
            for (int k = 0; k < 4; k++) acc[j][k] = 0.f;

        #pragma unroll
        for (int t = 0; t < 8; t++) {
            uint32_t a0 = Ah[4*t], a1 = Ah[4*t+1], a2 = Ah[4*t+2], a3 = Ah[4*t+3];
            #pragma unroll
            for (int j = 0; j < 8; j++) {
                uint2 bb = *(const uint2*)&Bcur[(8*j + r4)*BPH + 16*t + 4*c4];
                mma16(acc[j][0], acc[j][1], acc[j][2], acc[j][3],
                      a0, a1, a2, a3, bb.x, bb.y);
            }
        }

        const int n0 = colbase + nt * 64;
        #pragma unroll
        for (int j = 0; j < 8; j++) {
            int colg = n0 + 8*j + 2*c4;
            float2 bias = *(const float2*)&b_in[colg];
            float2 ws   = *(const float2*)&g_wsum[colg];
            float off0 = bias.x - mr * ws.x;
            float off1 = bias.y - mr * ws.y;
            float v00 = rstd*acc[j][0] + off0, v01 = rstd*acc[j][1] + off1;
            float v10 = rstd*acc[j][2] + off0, v11 = rstd*acc[j][3] + off1;
            int hh = colg / 384;
            int r  = colg - hh * 384;
            int which = r >> 7;
            int d = r & 127;
            size_t base = ((size_t)(b*NH + hh)) * NS * ND;
            if (which == 0) {
                *(__half2*)&g_qh[base + (size_t)slo * ND + d] =
                    __floats2half2_rn(v00 * SCALE, v01 * SCALE);
                *(__half2*)&g_qh[base + (size_t)shi * ND + d] =
                    __floats2half2_rn(v10 * SCALE, v11 * SCALE);
            } else if (which == 1) {
                int dl = d & 15;
                int sb = (dl < 8) ? (dl * 2) : ((dl - 8) * 2 + 2);
                int dp = (d & ~15) | sb;
                *(__half2*)&g_kh[base + (size_t)slo * ND + dp] = __floats2half2_rn(v00, v01);
                *(__half2*)&g_kh[base + (size_t)shi * ND + dp] = __floats2half2_rn(v10, v11);
            } else {
                // V: direct fp16 d-major slot16-s store (replaces vtrans).
                // Per warp per d: the 16 row-writes fill exactly one 32B sector.
                __half* vt = g_vth + base;
                vt[(size_t)d       * NS + splo] = __float2half_rn(v00);
                vt[(size_t)(d + 1) * NS + splo] = __float2half_rn(v01);
                vt[(size_t)d       * NS + sphi] = __float2half_rn(v10);
                vt[(size_t)(d + 1) * NS + sphi] = __float2half_rn(v11);
            }
        }

        if (nt + 1 < NTQ) {
            asm volatile("cp.async.wait_group 0;");
            __syncthreads();
        }
    }
}

// K4: out projection (fp16 mma)
__global__ __launch_bounds__(256, 2) void outproj_kernel(const float* __restrict__ b_out,
                                                         float* __restrict__ out) {
    extern __shared__ char sgc[];
    float* As = (float*)sgc;
    __half* Bs0 = (__half*)(sgc + 128*APJ*4);
    __half* Bs1 = Bs0 + 64*BPH;

    const int tid  = threadIdx.x;
    const int w    = tid >> 5;
    const int lane = tid & 31;
    const int r4   = lane >> 2;
    const int c4   = lane & 3;

    const int hh = blockIdx.x;
    const int m0 = blockIdx.y * 128;
    const int b  = blockIdx.y >> 3;
    const int s0 = m0 & (NS - 1);
    const float* Ag = g_ctx + ((size_t)(b*NH + hh) * NS + s0) * ND;
    const int colbase = hh * 128;

    #pragma unroll
    for (int i = 0; i < 16; i++) {
        int q = i * 256 + tid;
        int row = q >> 5, c = (q & 31) * 4;
        cp16(&As[row*APJ + c], &Ag[(size_t)row * ND + c]);
    }
    #pragma unroll
    for (int i = 0; i < 4; i++) {
        int q = i * 256 + tid;
        int row = q >> 4, c = (q & 15) * 8;
        cp16(&Bs0[row*BPH + c], &g_wout_h[(size_t)(colbase + row) * ND + c]);
    }
    asm volatile("cp.async.commit_group;");
    asm volatile("cp.async.wait_group 0;");
    __syncthreads();

    uint32_t Ah[32];
    {
        const int rl = 16*w + r4;
        #pragma unroll
        for (int t = 0; t < 8; t++) {
            float2 lo0 = *(const float2*)&As[(rl    )*APJ + 16*t + 2*c4    ];
            float2 lo1 = *(const float2*)&As[(rl + 8)*APJ + 16*t + 2*c4    ];
            float2 hi0 = *(const float2*)&As[(rl    )*APJ + 16*t + 2*c4 + 8];
            float2 hi1 = *(const float2*)&As[(rl + 8)*APJ + 16*t + 2*c4 + 8];
            Ah[4*t+0] = h2u(__floats2half2_rn(lo0.x, lo0.y));
            Ah[4*t+1] = h2u(__floats2half2_rn(lo1.x, lo1.y));
            Ah[4*t+2] = h2u(__floats2half2_rn(hi0.x, hi0.y));
            Ah[4*t+3] = h2u(__floats2half2_rn(hi1.x, hi1.y));
        }
    }

    const int rlo = m0 + 16*w + r4;
    const int rhi = rlo + 8;

    #pragma unroll
    for (int nt = 0; nt < 2; nt++) {
        __half* Bcur = nt ? Bs1 : Bs0;
        __half* Bnxt = nt ? Bs0 : Bs1;
        if (nt == 0) {
            const int nrow = colbase + 64;
            #pragma unroll
            for (int i = 0; i < 4; i++) {
                int q = i * 256 + tid;
                int row = q >> 4, c = (q & 15) * 8;
                cp16(&Bnxt[row*BPH + c], &g_wout_h[(size_t)(nrow + row) * ND + c]);
            }
            asm volatile("cp.async.commit_group;");
        }

        float acc[8][4];
        #pragma unroll
        for (int j = 0; j < 8; j++)
            #pragma unroll
            for (int k = 0; k < 4; k++) acc[j][k] = 0.f;

        #pragma unroll
        for (int t = 0; t < 8; t++) {
            uint32_t a0 = Ah[4*t], a1 = Ah[4*t+1], a2 = Ah[4*t+2], a3 = Ah[4*t+3];
            #pragma unroll
            for (int j = 0; j < 8; j++) {
                uint2 bb = *(const uint2*)&Bcur[(8*j + r4)*BPH + 16*t + 4*c4];
                mma16(acc[j][0], acc[j][1], acc[j][2], acc[j][3],
                      a0, a1, a2, a3, bb.x, bb.y);
            }
        }

        const int n0 = colbase + nt * 64;
        #pragma unroll
        for (int j = 0; j < 8; j++) {
            int colg = n0 + 8*j + 2*c4;
            float2 bias = *(const float2*)&b_out[colg];
            *(float2*)&out[(size_t)rlo * (NH*ND) + colg] =
                make_float2(acc[j][0] + bias.x, acc[j][1] + bias.y);
            *(float2*)&out[(size_t)rhi * (NH*ND) + colg] =
                make_float2(acc[j][2] + bias.x, acc[j][3] + bias.y);
        }

        if (nt == 0) {
            asm volatile("cp.async.wait_group 0;");
            __syncthreads();
        }
    }
}

// ---------------------------------------------------------------------------
// K3: flash attention (unchanged from R8/R9 — protect the win)
// ---------------------------------------------------------------------------
#define KPH 144
#define VPH 80
#define PPH 80
#define QSH 136
#define OFF_K   0
#define OFF_V   (4*64*KPH)
#define OFF_P   (OFF_V + 4*128*VPH)
#define OFF_QSTG (OFF_V + 128*VPH)
#define ATTN_SMEM_HALVES (OFF_P + 128*PPH)

__device__ __forceinline__ void load_kv_async(const __half* __restrict__ Kg,
                                              const __half* __restrict__ Vg,
                                              int n0, __half* Ks, __half* Vt, int tid) {
    #pragma unroll
    for (int i = 0; i < 4; i++) {
        int q = i * 256 + tid;
        int kr = q >> 4, kc = (q & 15) * 8;
        cp16(&Ks[kr*KPH + kc], Kg + (size_t)(n0 + kr) * ND + kc);
        int vr = q >> 3, vc = (q & 7) * 8;
        cp16(&Vt[vr*VPH + vc], Vg + (size_t)vr * NS + n0 + vc);
    }
}

__global__ __launch_bounds__(256, 1) void attn_kernel() {
    extern __shared__ __half smh[];
    const int tid  = threadIdx.x;
    const int w    = tid >> 5;
    const int lane = tid & 31;
    const int r4   = lane >> 2;
    const int c4   = lane & 3;

    const int bh = blockIdx.x >> 3;
    const int qt = blockIdx.x & 7;
    const int h  = bh & 3;
    const int m0 = qt * 128;

    const __half* Qg = g_qh  + (size_t)bh * NS * ND;
    const __half* Kg = g_kh  + (size_t)bh * NS * ND;
    const __half* Vg = g_vth + (size_t)bh * ND * NS;

    load_kv_async(Kg, Vg, 0, smh + OFF_K, smh + OFF_V, tid);
    asm volatile("cp.async.commit_group;");

    {
        __half* Qstg = smh + OFF_QSTG;
        #pragma unroll
        for (int i = 0; i < 8; i++) {
            int q = i * 256 + tid;
            int row = q >> 4, ch = (q & 15) * 8;
            *(uint4*)&Qstg[row*QSH + ch] =
                *(const uint4*)&Qg[(size_t)(m0 + row) * ND + ch];
        }
    }
    __syncthreads();

    uint32_t Qf[32];
    {
        const __half* Qstg = smh + OFF_QSTG;
        const int rl = 16*w + r4;
        #pragma unroll
        for (int t = 0; t < 8; t++) {
            Qf[4*t+0] = *(const uint32_t*)&Qstg[(rl    )*QSH + 16*t + 2*c4    ];
            Qf[4*t+1] = *(const uint32_t*)&Qstg[(rl + 8)*QSH + 16*t + 2*c4    ];
            Qf[4*t+2] = *(const uint32_t*)&Qstg[(rl    )*QSH + 16*t + 2*c4 + 8];
            Qf[4*t+3] = *(const uint32_t*)&Qstg[(rl + 8)*QSH + 16*t + 2*c4 + 8];
        }
    }
    __syncthreads();

    load_kv_async(Kg, Vg, 64,  smh + OFF_K + 1*64*KPH, smh + OFF_V + 1*128*VPH, tid);
    asm volatile("cp.async.commit_group;");
    load_kv_async(Kg, Vg, 128, smh + OFF_K + 2*64*KPH, smh + OFF_V + 2*128*VPH, tid);
    asm volatile("cp.async.commit_group;");

    float o[16][4];
    #pragma unroll
    for (int j = 0; j < 16; j++)
        #pragma unroll
        for (int k = 0; k < 4; k++) o[j][k] = 0.f;
    float rs_lo = 0.f, rs_hi = 0.f;

    __half* Psw = smh + OFF_P + (w * 16) * PPH;
    const int mlo = m0 + 16*w + r4;
    const int mhi = mlo + 8;
    const unsigned long long* mb_lo_base = &g_mbits[((size_t)h*NS + mlo)*16];
    const unsigned long long* mb_hi_base = &g_mbits[((size_t)h*NS + mhi)*16];

    for (int it = 0; it < 16; ++it) {
        if (it < 14)       { asm volatile("cp.async.wait_group 2;"); }
        else if (it == 14) { asm volatile("cp.async.wait_group 1;"); }
        else               { asm volatile("cp.async.wait_group 0;"); }
        __syncthreads();
        if (it + 3 < 16) {
            int nslot = (it + 3) & 3;
            load_kv_async(Kg, Vg, (it + 3) * 64,
                          smh + OFF_K + nslot*64*KPH,
                          smh + OFF_V + nslot*128*VPH, tid);
            asm volatile("cp.async.commit_group;");
        }

        const __half* Ks = smh + OFF_K + (it & 3) * 64 * KPH;
        const __half* Vt = smh + OFF_V + (it & 3) * 128 * VPH;
        const unsigned long long mb_lo = mb_lo_base[it];
        const unsigned long long mb_hi = mb_hi_base[it];

        float acc[8][4];
        #pragma unroll
        for (int j = 0; j < 8; j++)
            #pragma unroll
            for (int k = 0; k < 4; k++) acc[j][k] = 0.f;

        #pragma unroll
        for (int t = 0; t < 8; t++) {
            uint32_t a0 = Qf[4*t], a1 = Qf[4*t+1], a2 = Qf[4*t+2], a3 = Qf[4*t+3];
            #pragma unroll
            for (int j = 0; j < 8; j++) {
                uint2 bb = *(const uint2*)&Ks[(8*j + r4)*KPH + 16*t + 4*c4];
                mma16(acc[j][0], acc[j][1], acc[j][2], acc[j][3],
                      a0, a1, a2, a3, bb.x, bb.y);
            }
        }

        #pragma unroll
        for (int j = 0; j < 8; j++) {
            unsigned blo = (unsigned)(mb_lo >> (8*j + 2*c4));
            unsigned bhi = (unsigned)(mb_hi >> (8*j + 2*c4));
            float p0 = (blo & 1u) ? __expf(acc[j][0]) : 0.f;
            float p1 = (blo & 2u) ? __expf(acc[j][1]) : 0.f;
            float p2 = (bhi & 1u) ? __expf(acc[j][2]) : 0.f;
            float p3 = (bhi & 2u) ? __expf(acc[j][3]) : 0.f;
            __half2 hlo = __floats2half2_rn(p0, p1);
            __half2 hhi = __floats2half2_rn(p2, p3);
            float2 flo = __half22float2(hlo);
            float2 fhi = __half22float2(hhi);
            rs_lo += flo.x + flo.y;
            rs_hi += fhi.x + fhi.y;
            int off = (j >> 1) * 16 + 4*c4 + 2*(j & 1);
            *(__half2*)&Psw[(r4    )*PPH + off] = hlo;
            *(__half2*)&Psw[(r4 + 8)*PPH + off] = hhi;
        }
        __syncwarp();

        #pragma unroll
        for (int t = 0; t < 4; t++) {
            uint2 aLo = *(const uint2*)&Psw[(r4    )*PPH + 16*t + 4*c4];
            uint2 aHi = *(const uint2*)&Psw[(r4 + 8)*PPH + 16*t + 4*c4];
            #pragma unroll
            for (int j = 0; j < 16; j++) {
                uint2 bb = *(const uint2*)&Vt[(8*j + r4)*VPH + 16*t + 4*c4];
                mma16(o[j][0], o[j][1], o[j][2], o[j][3],
                      aLo.x, aHi.x, aLo.y, aHi.y, bb.x, bb.y);
            }
        }
    }

    rs_lo += __shfl_xor_sync(0xffffffffu, rs_lo, 1);
    rs_lo += __shfl_xor_sync(0xffffffffu, rs_lo, 2);
    rs_hi += __shfl_xor_sync(0xffffffffu, rs_hi, 1);
    rs_hi += __shfl_xor_sync(0xffffffffu, rs_hi, 2);
    float inv_lo = 1.f / rs_lo;
    float inv_hi = 1.f / rs_hi;
    #pragma unroll
    for (int j = 0; j < 16; j++) {
        int d = 8*j + 2*c4;
        size_t blo = ((size_t)bh * NS + mlo) * ND + d;
        size_t bhi = ((size_t)bh * NS + mhi) * ND + d;
        *(float2*)&g_ctx[blo] = make_float2(o[j][0] * inv_lo, o[j][1] * inv_lo);
        *(float2*)&g_ctx[bhi] = make_float2(o[j][2] * inv_hi, o[j][3] * inv_hi);
    }
}

// ---------------------------------------------------------------------------
extern "C" void kernel_launch(void* const* d_in, const int* in_sizes, int n_in,
                              void* d_out, int out_size) {
    const float* x     = (const float*)d_in[0];
    const int*   edge  = (const int*)d_in[1];
    const float* W_in  = (const float*)d_in[2];
    const float* b_in  = (const float*)d_in[3];
    const float* W_out = (const float*)d_in[4];
    const float* b_out = (const float*)d_in[5];
    float* out = (float*)d_out;

    static const size_t attn_smem = ATTN_SMEM_HALVES * sizeof(__half); // 176128
    static const size_t proj_smem = PROJ_SMEM_BYTES;                   // 104448
    cudaFuncSetAttribute((const void*)attn_kernel,
                         cudaFuncAttributeMaxDynamicSharedMemorySize, (int)attn_smem);
    cudaFuncSetAttribute((const void*)qkv_kernel,
                         cudaFuncAttributeMaxDynamicSharedMemorySize, (int)proj_smem);
    cudaFuncSetAttribute((const void*)outproj_kernel,
                         cudaFuncAttributeMaxDynamicSharedMemorySize, (int)proj_smem);

    ln_partial_kernel<<<NB*8, 256>>>(x);
    ln_final_kernel<<<1, 64>>>(edge);
    prep_kernel<<<78, 256>>>(edge, W_in, W_out);
    qkv_kernel<<<dim3(2, 128), 256, proj_smem>>>(x, b_in);
    attn_kernel<<<NB * NH * (NS / 128), 256, attn_smem>>>();
    outproj_kernel<<<dim3(4, 128), 256, proj_smem>>>(b_out, out);
}